// round 13
// baseline (speedup 1.0000x reference)
#include <cuda_runtime.h>
#include <cstdint>
#include <cstddef>
#include <math.h>

#define BATCH 16384
#define DIM   1024
#define NNODES (2*BATCH)

// ---------------- scratch (static device memory: allowed) ----------------
__device__ float g_pre    [(size_t)NNODES * DIM];      // proj out pre-LN (interleaved)
__device__ float g_nodes  [(size_t)NNODES * DIM];      // post LN+relu
__device__ float g_xmean1 [(size_t)BATCH * 2 * DIM];   // pair-mean of gat1 out (fused)
__device__ float g_x1row01[2 * 2 * DIM];               // exact x1 rows 0,1 (attention)
__device__ float g_xm0    [DIM];                       // exact xm row 0
__device__ float g_fcb    [(size_t)BATCH * DIM];       // fused gat2+fc out pre-LN
__device__ float g_w2t    [(size_t)2 * DIM * DIM];     // W2^T [2048,1024]
__device__ float g_wc     [(size_t)DIM * 2 * DIM];     // Wc = Wf @ W2  [1024,2048]
__device__ float g_bc     [DIM];                       // bc = Wf b2 + bf
__device__ float g_zb     [2 * DIM];                   // zero bias (static-zeroed)

__device__ __forceinline__ uint32_t tf32bits(float x) {
    uint32_t y;
    asm("cvt.rna.tf32.f32 %0, %1;" : "=r"(y) : "f"(x));
    return y;
}

__device__ __forceinline__ void cp_async16(uint32_t smem_dst, const void* gsrc) {
    asm volatile("cp.async.cg.shared.global [%0], [%1], 16;\n"
                 :: "r"(smem_dst), "l"(gsrc));
}

// ---------------- tf32 GEMM: C = A @ W^T (+bias, opt relu, opt pair-mean) ----------
// Block tile 128(M) x 128(N) x 16(K); 8 warps of 32x64; 4-stage cp.async ring;
// 2 CTAs per SM. cvt.rna.tf32 post-LDS. K within each k8 permuted (pos j <-> k=2j /
// 2j-7): float2 LDS (K-sum order-invariant).
// MEAN=1: C row r gets 0.5*(out[2r]+out[2r+1]) via shfl across lane^4 (after RELU).
#define BM2 128
#define BN2 128
#define BK2 16
#define NTHR 256
#define RSTRIDE 24
#define A_STG (BM2 * RSTRIDE)
#define B_STG (BM2 * RSTRIDE)
#define STG_FLOATS (A_STG + B_STG)
#define NSTAGE 4
#define SMEM_BYTES (NSTAGE * STG_FLOATS * 4)   // 98304 B

template<int RELU, int MEAN>
__launch_bounds__(NTHR, 2)
__global__ void gemm_big(const float* __restrict__ A, const float* __restrict__ W,
                         const float* __restrict__ bias, float* __restrict__ C,
                         int K, int ldc, int rowmul, int rowadd)
{
    extern __shared__ float smem[];

    const int tid  = threadIdx.x;
    const int warp = tid >> 5;
    const int lane = tid & 31;
    const int g    = lane >> 2;
    const int tg   = lane & 3;
    const int wm   = (warp & 3) * 32;
    const int wn   = (warp >> 2) * 64;
    const int mblk = blockIdx.y * BM2;
    const int nblk = blockIdx.x * BN2;

    uint32_t smem_base;
    {
        void* p = smem;
        smem_base = (uint32_t)__cvta_generic_to_shared(p);
    }

    float acc[2][8][4];
#pragma unroll
    for (int i = 0; i < 2; i++)
#pragma unroll
        for (int j = 0; j < 8; j++)
#pragma unroll
            for (int q = 0; q < 4; q++) acc[i][j][q] = 0.f;

    auto issue = [&](int st, int kb) {
        const int k0 = kb * BK2;
        const uint32_t stg = smem_base + (uint32_t)(st * STG_FLOATS) * 4u;
#pragma unroll
        for (int i = 0; i < 2; i++) {
            const int c  = tid + i * NTHR;
            const int m  = c >> 2;
            const int kc = (c & 3) * 4;
            cp_async16(stg + (uint32_t)(m * RSTRIDE + kc) * 4u,
                       A + (size_t)(mblk + m) * K + k0 + kc);
            cp_async16(stg + (uint32_t)(A_STG + m * RSTRIDE + kc) * 4u,
                       W + (size_t)(nblk + m) * K + k0 + kc);
        }
    };

    auto compute = [&](int st) {
        const float* Ast = smem + st * STG_FLOATS;
        const float* Bst = Ast + A_STG;
#pragma unroll
        for (int k8 = 0; k8 < 2; k8++) {
            const int kb8 = k8 * 8;
            uint32_t af[2][4];
#pragma unroll
            for (int i = 0; i < 2; i++) {
                const int m0 = wm + i * 16;
                const float2 lo = *(const float2*)(Ast + (m0 + g    ) * RSTRIDE + kb8 + 2 * tg);
                const float2 hi = *(const float2*)(Ast + (m0 + g + 8) * RSTRIDE + kb8 + 2 * tg);
                af[i][0] = tf32bits(lo.x);
                af[i][1] = tf32bits(hi.x);
                af[i][2] = tf32bits(lo.y);
                af[i][3] = tf32bits(hi.y);
            }
            uint32_t bfr[8][2];
#pragma unroll
            for (int j = 0; j < 8; j++) {
                const int n0 = wn + j * 8;
                const float2 b2v = *(const float2*)(Bst + (n0 + g) * RSTRIDE + kb8 + 2 * tg);
                bfr[j][0] = tf32bits(b2v.x);
                bfr[j][1] = tf32bits(b2v.y);
            }
#pragma unroll
            for (int i = 0; i < 2; i++)
#pragma unroll
                for (int j = 0; j < 8; j++)
                    asm volatile(
                        "mma.sync.aligned.m16n8k8.row.col.f32.tf32.tf32.f32 "
                        "{%0,%1,%2,%3}, {%4,%5,%6,%7}, {%8,%9}, {%0,%1,%2,%3};\n"
                        : "+f"(acc[i][j][0]), "+f"(acc[i][j][1]),
                          "+f"(acc[i][j][2]), "+f"(acc[i][j][3])
                        : "r"(af[i][0]), "r"(af[i][1]), "r"(af[i][2]), "r"(af[i][3]),
                          "r"(bfr[j][0]), "r"(bfr[j][1]));
        }
    };

    const int KT = K / BK2;

#pragma unroll
    for (int p = 0; p < NSTAGE - 1; p++) {
        if (p < KT) issue(p, p);
        asm volatile("cp.async.commit_group;\n" ::);
    }

    for (int kb = 0; kb < KT; kb++) {
        asm volatile("cp.async.wait_group %0;\n" :: "n"(NSTAGE - 2));
        __syncthreads();
        if (kb + NSTAGE - 1 < KT) issue((kb + NSTAGE - 1) % NSTAGE, kb + NSTAGE - 1);
        asm volatile("cp.async.commit_group;\n" ::);
        compute(kb % NSTAGE);
        __syncthreads();
    }

    // epilogue
#pragma unroll
    for (int i = 0; i < 2; i++) {
        const int row_a = mblk + wm + i * 16 + g;
        const int row_b = row_a + 8;
#pragma unroll
        for (int j = 0; j < 8; j++) {
            const int col = nblk + wn + j * 8 + 2 * tg;
            const float2 bv = *(const float2*)(bias + col);
            float o0 = acc[i][j][0] + bv.x;
            float o1 = acc[i][j][1] + bv.y;
            float o2 = acc[i][j][2] + bv.x;
            float o3 = acc[i][j][3] + bv.y;
            if (RELU) {
                o0 = fmaxf(o0, 0.f); o1 = fmaxf(o1, 0.f);
                o2 = fmaxf(o2, 0.f); o3 = fmaxf(o3, 0.f);
            }
            if (MEAN) {
                const float m0 = 0.5f * (o0 + __shfl_xor_sync(0xffffffffu, o0, 4));
                const float m1 = 0.5f * (o1 + __shfl_xor_sync(0xffffffffu, o1, 4));
                const float m2 = 0.5f * (o2 + __shfl_xor_sync(0xffffffffu, o2, 4));
                const float m3 = 0.5f * (o3 + __shfl_xor_sync(0xffffffffu, o3, 4));
                if ((g & 1) == 0) {
                    const size_t ra = (size_t)(row_a >> 1) * ldc + col;
                    const size_t rb = (size_t)(row_b >> 1) * ldc + col;
                    *(float2*)(C + ra) = make_float2(m0, m1);
                    *(float2*)(C + rb) = make_float2(m2, m3);
                }
            } else {
                const size_t ca = (size_t)(rowmul * row_a + rowadd) * ldc + col;
                const size_t cb = (size_t)(rowmul * row_b + rowadd) * ldc + col;
                *(float2*)(C + ca) = make_float2(o0, o1);
                *(float2*)(C + cb) = make_float2(o2, o3);
            }
        }
    }
}

// ---------------- 32x32 tiled transpose: out[C,R] = in[R,C]^T ----------------
__global__ void transpose_kernel(const float* __restrict__ in, float* __restrict__ out,
                                 int R, int C)
{
    __shared__ float tile[32][33];
    const int c0 = blockIdx.x * 32, r0 = blockIdx.y * 32;
    const int x = threadIdx.x, y = threadIdx.y;  // block (32, 8)
#pragma unroll
    for (int i = 0; i < 32; i += 8)
        tile[y + i][x] = in[(size_t)(r0 + y + i) * C + c0 + x];
    __syncthreads();
#pragma unroll
    for (int i = 0; i < 32; i += 8)
        out[(size_t)(c0 + y + i) * R + r0 + x] = tile[x][y + i];
}

// ---------------- bc = Wf @ b2 + bf  (1024 dots of length 1024) ----------------
__global__ void bc_kernel(const float* __restrict__ Wf, const float* __restrict__ b2,
                          const float* __restrict__ bf, float* __restrict__ bc)
{
    const int row  = blockIdx.x * 8 + (threadIdx.x >> 5);
    const int lane = threadIdx.x & 31;
    const float* wr = Wf + (size_t)row * DIM;
    float p = 0.f;
    for (int k = lane; k < DIM; k += 32) p += wr[k] * b2[k];
#pragma unroll
    for (int off = 16; off; off >>= 1) p += __shfl_xor_sync(0xffffffffu, p, off);
    if (lane == 0) bc[row] = p + bf[row];
}

// ---------------- LayerNorm (+opt relu), row length DIM ----------------
__global__ void ln_kernel(const float* __restrict__ in, float* __restrict__ out,
                          const float* __restrict__ g_e, const float* __restrict__ b_e,
                          const float* __restrict__ g_o, const float* __restrict__ b_o,
                          int relu)
{
    const int row = blockIdx.x;
    const int tid = threadIdx.x;
    const float* gg = (row & 1) ? g_o : g_e;
    const float* bb = (row & 1) ? b_o : b_e;

    float4 v = ((const float4*)(in + (size_t)row * DIM))[tid];
    float s = v.x + v.y + v.z + v.w;
    float q = v.x*v.x + v.y*v.y + v.z*v.z + v.w*v.w;
#pragma unroll
    for (int off = 16; off; off >>= 1) {
        s += __shfl_xor_sync(0xffffffffu, s, off);
        q += __shfl_xor_sync(0xffffffffu, q, off);
    }
    __shared__ float ss[8], sq[8];
    __shared__ float mu_s, rs_s;
    if ((tid & 31) == 0) { ss[tid >> 5] = s; sq[tid >> 5] = q; }
    __syncthreads();
    if (tid == 0) {
        float S = 0.f, Q = 0.f;
#pragma unroll
        for (int i = 0; i < 8; i++) { S += ss[i]; Q += sq[i]; }
        const float mu = S * (1.0f / DIM);
        const float var = Q * (1.0f / DIM) - mu * mu;
        mu_s = mu;
        rs_s = rsqrtf(var + 1e-5f);
    }
    __syncthreads();
    const float mu = mu_s, rs = rs_s;
    const float4 gv = ((const float4*)gg)[tid];
    const float4 bv = ((const float4*)bb)[tid];
    v.x = (v.x - mu) * rs * gv.x + bv.x;
    v.y = (v.y - mu) * rs * gv.y + bv.y;
    v.z = (v.z - mu) * rs * gv.z + bv.z;
    v.w = (v.w - mu) * rs * gv.w + bv.w;
    if (relu) {
        v.x = fmaxf(v.x, 0.f); v.y = fmaxf(v.y, 0.f);
        v.z = fmaxf(v.z, 0.f); v.w = fmaxf(v.w, 0.f);
    }
    ((float4*)(out + (size_t)row * DIM))[tid] = v;
}

__device__ __forceinline__ float lrelu(float v) { return v > 0.f ? v : 0.2f * v; }

// ---------------- GAT1 fixup rows 0,1: writes x1row01 + patches xmean1[0] --------
__global__ void fixup_gat1(const float* __restrict__ nodes, const float* __restrict__ W1,
                           const float* __restrict__ as1, const float* __restrict__ ad1,
                           const float* __restrict__ b1, float* __restrict__ x1row01,
                           float* __restrict__ xmean1)
{
    __shared__ float sh_n[2][DIM];
    __shared__ float sh_xp[2][2 * DIM];
    __shared__ float sh_sd[8];
    __shared__ float sh_w[8];
    const int tid = threadIdx.x, warp = tid >> 5, lane = tid & 31;

    for (int i = tid; i < 2 * DIM; i += 256) sh_n[i >> 10][i & 1023] = nodes[i];
    __syncthreads();

    for (int o = warp; o < 4096; o += 8) {
        const int n = o >> 11, oc = o & 2047;
        const float* wr = W1 + (size_t)oc * DIM;
        float p = 0.f;
        for (int k = lane; k < DIM; k += 32) p += sh_n[n][k] * wr[k];
#pragma unroll
        for (int off = 16; off; off >>= 1) p += __shfl_xor_sync(0xffffffffu, p, off);
        if (lane == 0) sh_xp[n][oc] = p;
    }
    __syncthreads();

    if (warp < 8) {
        const int n = warp >> 2, h = (warp >> 1) & 1, isd = warp & 1;
        const float* av = (isd ? ad1 : as1) + h * DIM;
        float p = 0.f;
        for (int k = lane; k < DIM; k += 32) p += sh_xp[n][h * DIM + k] * av[k];
#pragma unroll
        for (int off = 16; off; off >>= 1) p += __shfl_xor_sync(0xffffffffu, p, off);
        if (lane == 0) sh_sd[n * 4 + h * 2 + isd] = p;
    }
    __syncthreads();

    if (tid == 0) {
#pragma unroll
        for (int h = 0; h < 2; h++) {
            const float s0 = sh_sd[0*4 + h*2 + 0], d0 = sh_sd[0*4 + h*2 + 1];
            const float s1 = sh_sd[1*4 + h*2 + 0], d1 = sh_sd[1*4 + h*2 + 1];
            const float e00 = lrelu(s0 + d0), e10 = lrelu(s1 + d0);
            const float e11 = lrelu(s1 + d1), e01 = lrelu(s0 + d1);
            const float m0 = fmaxf(e00, e10);
            const float w00 = expf(e00 - m0), w10 = expf(e10 - m0);
            const float inv0 = 1.f / (w00 + w10);
            const float m1 = fmaxf(e11, e01);
            const float w11 = expf(e11 - m1), w01 = expf(e01 - m1);
            const float inv1 = 1.f / (w11 + w01);
            sh_w[h*4+0] = w00 * inv0;
            sh_w[h*4+1] = w10 * inv0;
            sh_w[h*4+2] = w11 * inv1;
            sh_w[h*4+3] = w01 * inv1;
        }
    }
    __syncthreads();

    for (int idx = tid; idx < 2 * DIM; idx += 256) {
        const int h = idx >> 10;
        const float o0 = sh_w[h*4+0] * sh_xp[0][idx] + sh_w[h*4+1] * sh_xp[1][idx];
        const float o1 = sh_w[h*4+2] * sh_xp[1][idx] + sh_w[h*4+3] * sh_xp[0][idx];
        const float r0 = fmaxf(o0 + b1[idx], 0.f);
        const float r1 = fmaxf(o1 + b1[idx], 0.f);
        x1row01[idx]           = r0;
        x1row01[2 * DIM + idx] = r1;
        xmean1[idx] = 0.5f * (r0 + r1);
    }
}

// ---------------- GAT2 fixup: exact xm row 0 from x1 rows 0,1 ----------------
__global__ void fixup_gat2(const float* __restrict__ x1row01, const float* __restrict__ W2,
                           const float* __restrict__ as2, const float* __restrict__ ad2,
                           const float* __restrict__ b2, float* __restrict__ xm0)
{
    __shared__ float sh_in[2][2 * DIM];
    __shared__ float sh_xp[2][DIM];
    __shared__ float sh_sd[4];
    __shared__ float sh_w[4];
    const int tid = threadIdx.x, warp = tid >> 5, lane = tid & 31;

    for (int i = tid; i < 4 * DIM; i += 256) sh_in[i >> 11][i & 2047] = x1row01[i];
    __syncthreads();

    for (int o = warp; o < 2048; o += 8) {
        const int n = o >> 10, oc = o & 1023;
        const float* wr = W2 + (size_t)oc * (2 * DIM);
        float p = 0.f;
        for (int k = lane; k < 2 * DIM; k += 32) p += sh_in[n][k] * wr[k];
#pragma unroll
        for (int off = 16; off; off >>= 1) p += __shfl_xor_sync(0xffffffffu, p, off);
        if (lane == 0) sh_xp[n][oc] = p;
    }
    __syncthreads();

    if (warp < 4) {
        const int n = warp >> 1, isd = warp & 1;
        const float* av = isd ? ad2 : as2;
        float p = 0.f;
        for (int k = lane; k < DIM; k += 32) p += sh_xp[n][k] * av[k];
#pragma unroll
        for (int off = 16; off; off >>= 1) p += __shfl_xor_sync(0xffffffffu, p, off);
        if (lane == 0) sh_sd[n * 2 + isd] = p;
    }
    __syncthreads();

    if (tid == 0) {
        const float s0 = sh_sd[0], d0 = sh_sd[1], s1 = sh_sd[2], d1 = sh_sd[3];
        const float e00 = lrelu(s0 + d0), e10 = lrelu(s1 + d0);
        const float e11 = lrelu(s1 + d1), e01 = lrelu(s0 + d1);
        const float m0 = fmaxf(e00, e10);
        const float w00 = expf(e00 - m0), w10 = expf(e10 - m0);
        const float inv0 = 1.f / (w00 + w10);
        const float m1 = fmaxf(e11, e01);
        const float w11 = expf(e11 - m1), w01 = expf(e01 - m1);
        const float inv1 = 1.f / (w11 + w01);
        sh_w[0] = w00 * inv0; sh_w[1] = w10 * inv0;
        sh_w[2] = w11 * inv1; sh_w[3] = w01 * inv1;
    }
    __syncthreads();

    for (int idx = tid; idx < DIM; idx += 256) {
        const float o0 = sh_w[0] * sh_xp[0][idx] + sh_w[1] * sh_xp[1][idx] + b2[idx];
        const float o1 = sh_w[2] * sh_xp[1][idx] + sh_w[3] * sh_xp[0][idx] + b2[idx];
        xm0[idx] = 0.5f * (o0 + o1);
    }
}

// ---------------- FC fixup: fcb[0] = xm0 @ Wf^T + bf ----------------
__global__ void fixup_fc(const float* __restrict__ xm0, const float* __restrict__ Wf,
                         const float* __restrict__ bf, float* __restrict__ fcb)
{
    __shared__ float sh[DIM];
    const int tid = threadIdx.x, warp = tid >> 5, lane = tid & 31;
    for (int i = tid; i < DIM; i += 256) sh[i] = xm0[i];
    __syncthreads();
    for (int o = warp; o < DIM; o += 8) {
        const float* wr = Wf + (size_t)o * DIM;
        float p = 0.f;
        for (int k = lane; k < DIM; k += 32) p += sh[k] * wr[k];
#pragma unroll
        for (int off = 16; off; off >>= 1) p += __shfl_xor_sync(0xffffffffu, p, off);
        if (lane == 0) fcb[o] = p + bf[o];
    }
}

// ---------------- launch ----------------
extern "C" void kernel_launch(void* const* d_in, const int* in_sizes, int n_in,
                              void* d_out, int out_size)
{
    const float* audio = (const float*)d_in[0];
    const float* text  = (const float*)d_in[1];
    const float* Wa    = (const float*)d_in[2];
    const float* ba    = (const float*)d_in[3];
    const float* lna_g = (const float*)d_in[4];
    const float* lna_b = (const float*)d_in[5];
    const float* Wt    = (const float*)d_in[6];
    const float* bt    = (const float*)d_in[7];
    const float* lnt_g = (const float*)d_in[8];
    const float* lnt_b = (const float*)d_in[9];
    const float* W1    = (const float*)d_in[10];
    const float* as1   = (const float*)d_in[11];
    const float* ad1   = (const float*)d_in[12];
    const float* b1    = (const float*)d_in[13];
    const float* W2    = (const float*)d_in[14];
    const float* as2   = (const float*)d_in[15];
    const float* ad2   = (const float*)d_in[16];
    const float* b2    = (const float*)d_in[17];
    const float* Wf    = (const float*)d_in[18];
    const float* bf    = (const float*)d_in[19];
    const float* lnf_g = (const float*)d_in[20];
    const float* lnf_b = (const float*)d_in[21];

    float *pre, *nodes, *xmean1, *x1row01, *xm0, *fcb, *w2t, *wc, *bc, *zb;
    cudaGetSymbolAddress((void**)&pre,     g_pre);
    cudaGetSymbolAddress((void**)&nodes,   g_nodes);
    cudaGetSymbolAddress((void**)&xmean1,  g_xmean1);
    cudaGetSymbolAddress((void**)&x1row01, g_x1row01);
    cudaGetSymbolAddress((void**)&xm0,     g_xm0);
    cudaGetSymbolAddress((void**)&fcb,     g_fcb);
    cudaGetSymbolAddress((void**)&w2t,     g_w2t);
    cudaGetSymbolAddress((void**)&wc,      g_wc);
    cudaGetSymbolAddress((void**)&bc,      g_bc);
    cudaGetSymbolAddress((void**)&zb,      g_zb);

    cudaFuncSetAttribute(gemm_big<0,0>, cudaFuncAttributeMaxDynamicSharedMemorySize, SMEM_BYTES);
    cudaFuncSetAttribute(gemm_big<1,1>, cudaFuncAttributeMaxDynamicSharedMemorySize, SMEM_BYTES);

    dim3 blk(NTHR);

    // --- precompute fused gat2+fc weights: Wc = Wf @ W2, bc = Wf b2 + bf ---
    transpose_kernel<<<dim3(64, 32), dim3(32, 8)>>>(W2, w2t, DIM, 2 * DIM);   // w2t[2048,1024]
    gemm_big<0,0><<<dim3(16, 8), blk, SMEM_BYTES>>>(Wf, w2t, zb, wc, 1024, 2048, 1, 0);
    bc_kernel<<<128, 256>>>(Wf, b2, bf, bc);

    // proj_audio / proj_text -> interleaved pre-LN rows (row = 2*m + {0,1})
    gemm_big<0,0><<<dim3(8, 128), blk, SMEM_BYTES>>>(audio, Wa, ba, pre, 1024, 1024, 2, 0);
    gemm_big<0,0><<<dim3(8, 128), blk, SMEM_BYTES>>>(text,  Wt, bt, pre, 1024, 1024, 2, 1);
    // LN + relu (gain/bias by row parity)
    ln_kernel<<<NNODES, 256>>>(pre, nodes, lna_g, lna_b, lnt_g, lnt_b, 1);
    // gat1 self-loop path + relu + FUSED pair-mean -> xmean1 [BATCH, 2*DIM]
    gemm_big<1,1><<<dim3(16, 256), blk, SMEM_BYTES>>>(nodes, W1, b1, xmean1, 1024, 2048, 1, 0);
    // exact attention x1 rows 0,1 + patch xmean1 row 0 (before fused GEMM)
    fixup_gat1<<<1, 256>>>(nodes, W1, as1, ad1, b1, x1row01, xmean1);
    // FUSED gat2+fc: fcb = xmean1 @ Wc^T + bc
    gemm_big<0,0><<<dim3(8, 128), blk, SMEM_BYTES>>>(xmean1, wc, bc, fcb, 2048, 1024, 1, 0);
    // exact xm row 0, then patch fcb row 0
    fixup_gat2<<<1, 256>>>(x1row01, W2, as2, ad2, b2, xm0);
    fixup_fc<<<1, 256>>>(xm0, Wf, bf, fcb);
    // final LN -> out
    ln_kernel<<<BATCH, 256>>>(fcb, (float*)d_out, lnf_g, lnf_b, lnf_g, lnf_b, 0);
}

// round 14
// speedup vs baseline: 1.1071x; 1.1071x over previous
#include <cuda_runtime.h>
#include <cstdint>
#include <cstddef>
#include <math.h>

#define BATCH 16384
#define DIM   1024
#define NNODES (2*BATCH)

// ---------------- scratch (static device memory: allowed) ----------------
__device__ float g_pre    [(size_t)NNODES * DIM];      // proj out pre-LN (interleaved)
__device__ float g_nodes  [(size_t)NNODES * DIM];      // post LN+relu
__device__ float g_xmean1 [(size_t)BATCH * 2 * DIM];   // pair-mean of gat1 out (fused)
__device__ float g_x1row01[2 * 2 * DIM];               // exact x1 rows 0,1 (attention)
__device__ float g_xm     [(size_t)BATCH * DIM];       // gat2 out on xmean1
__device__ float g_fcb    [(size_t)BATCH * DIM];       // fc out pre-LN

__device__ __forceinline__ uint32_t tf32bits(float x) {
    uint32_t y;
    asm("cvt.rna.tf32.f32 %0, %1;" : "=r"(y) : "f"(x));
    return y;
}

__device__ __forceinline__ void cp_async16(uint32_t smem_dst, const void* gsrc) {
    asm volatile("cp.async.cg.shared.global [%0], [%1], 16;\n"
                 :: "r"(smem_dst), "l"(gsrc));
}

// ---------------- tf32 GEMM: C = A @ W^T (+bias, opt relu, opt pair-mean) ----------
// Block tile 128(M) x 128(N) x 16(K); 8 warps of 32x64; 4-stage cp.async ring;
// 2 CTAs per SM. cvt.rna.tf32 post-LDS. K within each k8 permuted (pos j <-> k=2j /
// 2j-7): float2 LDS (K-sum order-invariant).
// MEAN=1: C row r gets 0.5*(out[2r]+out[2r+1]) via shfl across lane^4 (after RELU).
#define BM2 128
#define BN2 128
#define BK2 16
#define NTHR 256
#define RSTRIDE 24
#define A_STG (BM2 * RSTRIDE)
#define B_STG (BM2 * RSTRIDE)
#define STG_FLOATS (A_STG + B_STG)
#define NSTAGE 4
#define SMEM_BYTES (NSTAGE * STG_FLOATS * 4)   // 98304 B

template<int RELU, int MEAN>
__launch_bounds__(NTHR, 2)
__global__ void gemm_big(const float* __restrict__ A, const float* __restrict__ W,
                         const float* __restrict__ bias, float* __restrict__ C,
                         int K, int ldc, int rowmul, int rowadd)
{
    extern __shared__ float smem[];

    const int tid  = threadIdx.x;
    const int warp = tid >> 5;
    const int lane = tid & 31;
    const int g    = lane >> 2;
    const int tg   = lane & 3;
    const int wm   = (warp & 3) * 32;
    const int wn   = (warp >> 2) * 64;
    const int mblk = blockIdx.y * BM2;
    const int nblk = blockIdx.x * BN2;

    uint32_t smem_base;
    {
        void* p = smem;
        smem_base = (uint32_t)__cvta_generic_to_shared(p);
    }

    float acc[2][8][4];
#pragma unroll
    for (int i = 0; i < 2; i++)
#pragma unroll
        for (int j = 0; j < 8; j++)
#pragma unroll
            for (int q = 0; q < 4; q++) acc[i][j][q] = 0.f;

    auto issue = [&](int st, int kb) {
        const int k0 = kb * BK2;
        const uint32_t stg = smem_base + (uint32_t)(st * STG_FLOATS) * 4u;
#pragma unroll
        for (int i = 0; i < 2; i++) {
            const int c  = tid + i * NTHR;
            const int m  = c >> 2;
            const int kc = (c & 3) * 4;
            cp_async16(stg + (uint32_t)(m * RSTRIDE + kc) * 4u,
                       A + (size_t)(mblk + m) * K + k0 + kc);
            cp_async16(stg + (uint32_t)(A_STG + m * RSTRIDE + kc) * 4u,
                       W + (size_t)(nblk + m) * K + k0 + kc);
        }
    };

    auto compute = [&](int st) {
        const float* Ast = smem + st * STG_FLOATS;
        const float* Bst = Ast + A_STG;
#pragma unroll
        for (int k8 = 0; k8 < 2; k8++) {
            const int kb8 = k8 * 8;
            uint32_t af[2][4];
#pragma unroll
            for (int i = 0; i < 2; i++) {
                const int m0 = wm + i * 16;
                const float2 lo = *(const float2*)(Ast + (m0 + g    ) * RSTRIDE + kb8 + 2 * tg);
                const float2 hi = *(const float2*)(Ast + (m0 + g + 8) * RSTRIDE + kb8 + 2 * tg);
                af[i][0] = tf32bits(lo.x);
                af[i][1] = tf32bits(hi.x);
                af[i][2] = tf32bits(lo.y);
                af[i][3] = tf32bits(hi.y);
            }
            uint32_t bfr[8][2];
#pragma unroll
            for (int j = 0; j < 8; j++) {
                const int n0 = wn + j * 8;
                const float2 b2v = *(const float2*)(Bst + (n0 + g) * RSTRIDE + kb8 + 2 * tg);
                bfr[j][0] = tf32bits(b2v.x);
                bfr[j][1] = tf32bits(b2v.y);
            }
#pragma unroll
            for (int i = 0; i < 2; i++)
#pragma unroll
                for (int j = 0; j < 8; j++)
                    asm volatile(
                        "mma.sync.aligned.m16n8k8.row.col.f32.tf32.tf32.f32 "
                        "{%0,%1,%2,%3}, {%4,%5,%6,%7}, {%8,%9}, {%0,%1,%2,%3};\n"
                        : "+f"(acc[i][j][0]), "+f"(acc[i][j][1]),
                          "+f"(acc[i][j][2]), "+f"(acc[i][j][3])
                        : "r"(af[i][0]), "r"(af[i][1]), "r"(af[i][2]), "r"(af[i][3]),
                          "r"(bfr[j][0]), "r"(bfr[j][1]));
        }
    };

    const int KT = K / BK2;

#pragma unroll
    for (int p = 0; p < NSTAGE - 1; p++) {
        if (p < KT) issue(p, p);
        asm volatile("cp.async.commit_group;\n" ::);
    }

    for (int kb = 0; kb < KT; kb++) {
        asm volatile("cp.async.wait_group %0;\n" :: "n"(NSTAGE - 2));
        __syncthreads();
        if (kb + NSTAGE - 1 < KT) issue((kb + NSTAGE - 1) % NSTAGE, kb + NSTAGE - 1);
        asm volatile("cp.async.commit_group;\n" ::);
        compute(kb % NSTAGE);
        __syncthreads();
    }

    // epilogue
#pragma unroll
    for (int i = 0; i < 2; i++) {
        const int row_a = mblk + wm + i * 16 + g;
        const int row_b = row_a + 8;
#pragma unroll
        for (int j = 0; j < 8; j++) {
            const int col = nblk + wn + j * 8 + 2 * tg;
            const float2 bv = *(const float2*)(bias + col);
            float o0 = acc[i][j][0] + bv.x;
            float o1 = acc[i][j][1] + bv.y;
            float o2 = acc[i][j][2] + bv.x;
            float o3 = acc[i][j][3] + bv.y;
            if (RELU) {
                o0 = fmaxf(o0, 0.f); o1 = fmaxf(o1, 0.f);
                o2 = fmaxf(o2, 0.f); o3 = fmaxf(o3, 0.f);
            }
            if (MEAN) {
                const float m0 = 0.5f * (o0 + __shfl_xor_sync(0xffffffffu, o0, 4));
                const float m1 = 0.5f * (o1 + __shfl_xor_sync(0xffffffffu, o1, 4));
                const float m2 = 0.5f * (o2 + __shfl_xor_sync(0xffffffffu, o2, 4));
                const float m3 = 0.5f * (o3 + __shfl_xor_sync(0xffffffffu, o3, 4));
                if ((g & 1) == 0) {
                    const size_t ra = (size_t)(row_a >> 1) * ldc + col;
                    const size_t rb = (size_t)(row_b >> 1) * ldc + col;
                    *(float2*)(C + ra) = make_float2(m0, m1);
                    *(float2*)(C + rb) = make_float2(m2, m3);
                }
            } else {
                const size_t ca = (size_t)(rowmul * row_a + rowadd) * ldc + col;
                const size_t cb = (size_t)(rowmul * row_b + rowadd) * ldc + col;
                *(float2*)(C + ca) = make_float2(o0, o1);
                *(float2*)(C + cb) = make_float2(o2, o3);
            }
        }
    }
}

// ---------------- LayerNorm, warp-per-row (no block barriers) ----------------
// Each warp owns one row of DIM=1024 floats (256 float4; 8 float4/lane).
// 256-thread block = 8 rows. Gains/bias selected by row parity.
__global__ void ln_kernel(const float* __restrict__ in, float* __restrict__ out,
                          const float* __restrict__ g_e, const float* __restrict__ b_e,
                          const float* __restrict__ g_o, const float* __restrict__ b_o,
                          int relu)
{
    const int warp = threadIdx.x >> 5;
    const int lane = threadIdx.x & 31;
    const int row  = blockIdx.x * 8 + warp;
    const float* gg = (row & 1) ? g_o : g_e;
    const float* bb = (row & 1) ? b_o : b_e;

    const float4* rin = (const float4*)(in + (size_t)row * DIM);
    float4 v[8];
    float s = 0.f, q = 0.f;
#pragma unroll
    for (int i = 0; i < 8; i++) {
        v[i] = rin[lane + 32 * i];
        s += v[i].x + v[i].y + v[i].z + v[i].w;
        q += v[i].x*v[i].x + v[i].y*v[i].y + v[i].z*v[i].z + v[i].w*v[i].w;
    }
#pragma unroll
    for (int off = 16; off; off >>= 1) {
        s += __shfl_xor_sync(0xffffffffu, s, off);
        q += __shfl_xor_sync(0xffffffffu, q, off);
    }
    const float mu = s * (1.0f / DIM);
    const float var = q * (1.0f / DIM) - mu * mu;
    const float rs = rsqrtf(var + 1e-5f);

    float4* rout = (float4*)(out + (size_t)row * DIM);
#pragma unroll
    for (int i = 0; i < 8; i++) {
        const int c4 = lane + 32 * i;
        const float4 gv = ((const float4*)gg)[c4];
        const float4 bv = ((const float4*)bb)[c4];
        float4 o;
        o.x = (v[i].x - mu) * rs * gv.x + bv.x;
        o.y = (v[i].y - mu) * rs * gv.y + bv.y;
        o.z = (v[i].z - mu) * rs * gv.z + bv.z;
        o.w = (v[i].w - mu) * rs * gv.w + bv.w;
        if (relu) {
            o.x = fmaxf(o.x, 0.f); o.y = fmaxf(o.y, 0.f);
            o.z = fmaxf(o.z, 0.f); o.w = fmaxf(o.w, 0.f);
        }
        rout[c4] = o;
    }
}

__device__ __forceinline__ float lrelu(float v) { return v > 0.f ? v : 0.2f * v; }

// ---------------- GAT1 fixup rows 0,1: writes x1row01 + patches xmean1[0] --------
__global__ void fixup_gat1(const float* __restrict__ nodes, const float* __restrict__ W1,
                           const float* __restrict__ as1, const float* __restrict__ ad1,
                           const float* __restrict__ b1, float* __restrict__ x1row01,
                           float* __restrict__ xmean1)
{
    __shared__ float sh_n[2][DIM];
    __shared__ float sh_xp[2][2 * DIM];
    __shared__ float sh_sd[8];
    __shared__ float sh_w[8];
    const int tid = threadIdx.x, warp = tid >> 5, lane = tid & 31;

    for (int i = tid; i < 2 * DIM; i += 256) sh_n[i >> 10][i & 1023] = nodes[i];
    __syncthreads();

    for (int o = warp; o < 4096; o += 8) {
        const int n = o >> 11, oc = o & 2047;
        const float* wr = W1 + (size_t)oc * DIM;
        float p = 0.f;
        for (int k = lane; k < DIM; k += 32) p += sh_n[n][k] * wr[k];
#pragma unroll
        for (int off = 16; off; off >>= 1) p += __shfl_xor_sync(0xffffffffu, p, off);
        if (lane == 0) sh_xp[n][oc] = p;
    }
    __syncthreads();

    if (warp < 8) {
        const int n = warp >> 2, h = (warp >> 1) & 1, isd = warp & 1;
        const float* av = (isd ? ad1 : as1) + h * DIM;
        float p = 0.f;
        for (int k = lane; k < DIM; k += 32) p += sh_xp[n][h * DIM + k] * av[k];
#pragma unroll
        for (int off = 16; off; off >>= 1) p += __shfl_xor_sync(0xffffffffu, p, off);
        if (lane == 0) sh_sd[n * 4 + h * 2 + isd] = p;
    }
    __syncthreads();

    if (tid == 0) {
#pragma unroll
        for (int h = 0; h < 2; h++) {
            const float s0 = sh_sd[0*4 + h*2 + 0], d0 = sh_sd[0*4 + h*2 + 1];
            const float s1 = sh_sd[1*4 + h*2 + 0], d1 = sh_sd[1*4 + h*2 + 1];
            const float e00 = lrelu(s0 + d0), e10 = lrelu(s1 + d0);
            const float e11 = lrelu(s1 + d1), e01 = lrelu(s0 + d1);
            const float m0 = fmaxf(e00, e10);
            const float w00 = expf(e00 - m0), w10 = expf(e10 - m0);
            const float inv0 = 1.f / (w00 + w10);
            const float m1 = fmaxf(e11, e01);
            const float w11 = expf(e11 - m1), w01 = expf(e01 - m1);
            const float inv1 = 1.f / (w11 + w01);
            sh_w[h*4+0] = w00 * inv0;
            sh_w[h*4+1] = w10 * inv0;
            sh_w[h*4+2] = w11 * inv1;
            sh_w[h*4+3] = w01 * inv1;
        }
    }
    __syncthreads();

    for (int idx = tid; idx < 2 * DIM; idx += 256) {
        const int h = idx >> 10;
        const float o0 = sh_w[h*4+0] * sh_xp[0][idx] + sh_w[h*4+1] * sh_xp[1][idx];
        const float o1 = sh_w[h*4+2] * sh_xp[1][idx] + sh_w[h*4+3] * sh_xp[0][idx];
        const float r0 = fmaxf(o0 + b1[idx], 0.f);
        const float r1 = fmaxf(o1 + b1[idx], 0.f);
        x1row01[idx]           = r0;
        x1row01[2 * DIM + idx] = r1;
        xmean1[idx] = 0.5f * (r0 + r1);
    }
}

// ---------------- GAT2 fixup: exact xm row 0 from x1 rows 0,1 ----------------
__global__ void fixup_gat2(const float* __restrict__ x1row01, const float* __restrict__ W2,
                           const float* __restrict__ as2, const float* __restrict__ ad2,
                           const float* __restrict__ b2, float* __restrict__ xm)
{
    __shared__ float sh_in[2][2 * DIM];
    __shared__ float sh_xp[2][DIM];
    __shared__ float sh_sd[4];
    __shared__ float sh_w[4];
    const int tid = threadIdx.x, warp = tid >> 5, lane = tid & 31;

    for (int i = tid; i < 4 * DIM; i += 256) sh_in[i >> 11][i & 2047] = x1row01[i];
    __syncthreads();

    for (int o = warp; o < 2048; o += 8) {
        const int n = o >> 10, oc = o & 1023;
        const float* wr = W2 + (size_t)oc * (2 * DIM);
        float p = 0.f;
        for (int k = lane; k < 2 * DIM; k += 32) p += sh_in[n][k] * wr[k];
#pragma unroll
        for (int off = 16; off; off >>= 1) p += __shfl_xor_sync(0xffffffffu, p, off);
        if (lane == 0) sh_xp[n][oc] = p;
    }
    __syncthreads();

    if (warp < 4) {
        const int n = warp >> 1, isd = warp & 1;
        const float* av = isd ? ad2 : as2;
        float p = 0.f;
        for (int k = lane; k < DIM; k += 32) p += sh_xp[n][k] * av[k];
#pragma unroll
        for (int off = 16; off; off >>= 1) p += __shfl_xor_sync(0xffffffffu, p, off);
        if (lane == 0) sh_sd[n * 2 + isd] = p;
    }
    __syncthreads();

    if (tid == 0) {
        const float s0 = sh_sd[0], d0 = sh_sd[1], s1 = sh_sd[2], d1 = sh_sd[3];
        const float e00 = lrelu(s0 + d0), e10 = lrelu(s1 + d0);
        const float e11 = lrelu(s1 + d1), e01 = lrelu(s0 + d1);
        const float m0 = fmaxf(e00, e10);
        const float w00 = expf(e00 - m0), w10 = expf(e10 - m0);
        const float inv0 = 1.f / (w00 + w10);
        const float m1 = fmaxf(e11, e01);
        const float w11 = expf(e11 - m1), w01 = expf(e01 - m1);
        const float inv1 = 1.f / (w11 + w01);
        sh_w[0] = w00 * inv0; sh_w[1] = w10 * inv0;
        sh_w[2] = w11 * inv1; sh_w[3] = w01 * inv1;
    }
    __syncthreads();

    for (int idx = tid; idx < DIM; idx += 256) {
        const float o0 = sh_w[0] * sh_xp[0][idx] + sh_w[1] * sh_xp[1][idx] + b2[idx];
        const float o1 = sh_w[2] * sh_xp[1][idx] + sh_w[3] * sh_xp[0][idx] + b2[idx];
        xm[idx] = 0.5f * (o0 + o1);   // exact pair-mean for batch element 0
    }
}

// ---------------- launch ----------------
extern "C" void kernel_launch(void* const* d_in, const int* in_sizes, int n_in,
                              void* d_out, int out_size)
{
    const float* audio = (const float*)d_in[0];
    const float* text  = (const float*)d_in[1];
    const float* Wa    = (const float*)d_in[2];
    const float* ba    = (const float*)d_in[3];
    const float* lna_g = (const float*)d_in[4];
    const float* lna_b = (const float*)d_in[5];
    const float* Wt    = (const float*)d_in[6];
    const float* bt    = (const float*)d_in[7];
    const float* lnt_g = (const float*)d_in[8];
    const float* lnt_b = (const float*)d_in[9];
    const float* W1    = (const float*)d_in[10];
    const float* as1   = (const float*)d_in[11];
    const float* ad1   = (const float*)d_in[12];
    const float* b1    = (const float*)d_in[13];
    const float* W2    = (const float*)d_in[14];
    const float* as2   = (const float*)d_in[15];
    const float* ad2   = (const float*)d_in[16];
    const float* b2    = (const float*)d_in[17];
    const float* Wf    = (const float*)d_in[18];
    const float* bf    = (const float*)d_in[19];
    const float* lnf_g = (const float*)d_in[20];
    const float* lnf_b = (const float*)d_in[21];

    float *pre, *nodes, *xmean1, *x1row01, *xm, *fcb;
    cudaGetSymbolAddress((void**)&pre,     g_pre);
    cudaGetSymbolAddress((void**)&nodes,   g_nodes);
    cudaGetSymbolAddress((void**)&xmean1,  g_xmean1);
    cudaGetSymbolAddress((void**)&x1row01, g_x1row01);
    cudaGetSymbolAddress((void**)&xm,      g_xm);
    cudaGetSymbolAddress((void**)&fcb,     g_fcb);

    cudaFuncSetAttribute(gemm_big<0,0>, cudaFuncAttributeMaxDynamicSharedMemorySize, SMEM_BYTES);
    cudaFuncSetAttribute(gemm_big<1,1>, cudaFuncAttributeMaxDynamicSharedMemorySize, SMEM_BYTES);

    dim3 blk(NTHR);

    // proj_audio / proj_text -> interleaved pre-LN rows (row = 2*m + {0,1})
    gemm_big<0,0><<<dim3(8, 128), blk, SMEM_BYTES>>>(audio, Wa, ba, pre, 1024, 1024, 2, 0);
    gemm_big<0,0><<<dim3(8, 128), blk, SMEM_BYTES>>>(text,  Wt, bt, pre, 1024, 1024, 2, 1);
    // LN + relu (warp-per-row; gain/bias by row parity)
    ln_kernel<<<NNODES / 8, 256>>>(pre, nodes, lna_g, lna_b, lnt_g, lnt_b, 1);
    // gat1 self-loop path + relu + FUSED pair-mean -> xmean1 [BATCH, 2*DIM]
    gemm_big<1,1><<<dim3(16, 256), blk, SMEM_BYTES>>>(nodes, W1, b1, xmean1, 1024, 2048, 1, 0);
    // exact attention x1 rows 0,1 + patch xmean1 row 0 (before gat2 GEMM)
    fixup_gat1<<<1, 256>>>(nodes, W1, as1, ad1, b1, x1row01, xmean1);
    // gat2 on pre-meaned input (affine => mean commutes): xm = xmean1 @ W2^T + b2
    gemm_big<0,0><<<dim3(8, 128), blk, SMEM_BYTES>>>(xmean1, W2, b2, xm, 2048, 1024, 1, 0);
    // exact xm row 0 (after gat2 GEMM)
    fixup_gat2<<<1, 256>>>(x1row01, W2, as2, ad2, b2, xm);
    // fc on xm
    gemm_big<0,0><<<dim3(8, 128), blk, SMEM_BYTES>>>(xm, Wf, bf, fcb, 1024, 1024, 1, 0);
    // final LN -> out (warp-per-row)
    ln_kernel<<<BATCH / 8, 256>>>(fcb, (float*)d_out, lnf_g, lnf_b, lnf_g, lnf_b, 0);
}

// round 15
// speedup vs baseline: 2.8031x; 2.5319x over previous
#include <cuda_runtime.h>
#include <cuda_fp16.h>
#include <cstdint>
#include <cstddef>
#include <math.h>

#define BATCH 16384
#define DIM   1024
#define NNODES (2*BATCH)

// ---------------- scratch (static device memory: allowed) ----------------
__device__ __half g_audio_h[(size_t)BATCH * DIM];
__device__ __half g_text_h [(size_t)BATCH * DIM];
__device__ __half g_Wa_h   [(size_t)DIM * DIM];
__device__ __half g_Wt_h   [(size_t)DIM * DIM];
__device__ __half g_W1_h   [(size_t)2 * DIM * DIM];
__device__ __half g_W2_h   [(size_t)DIM * 2 * DIM];
__device__ __half g_Wf_h   [(size_t)DIM * DIM];
__device__ float  g_pre    [(size_t)NNODES * DIM];     // proj out pre-LN (interleaved)
__device__ __half g_nodes_h[(size_t)NNODES * DIM];     // post LN+relu (fp16)
__device__ __half g_xmean1h[(size_t)BATCH * 2 * DIM];  // pair-mean of gat1 out (fp16)
__device__ float  g_x1row01[2 * 2 * DIM];              // exact x1 rows 0,1 (fp32)
__device__ float  g_xp1    [2 * 2 * DIM];              // gat1 xp for rows 0,1
__device__ float  g_xp2    [2 * DIM];                  // gat2 xp for rows 0,1
__device__ __half g_xm_h   [(size_t)BATCH * DIM];      // gat2 out (fp16)
__device__ float  g_fcb    [(size_t)BATCH * DIM];      // fc out pre-LN (fp32)

__device__ __forceinline__ void cp_async16(uint32_t smem_dst, const void* gsrc) {
    asm volatile("cp.async.cg.shared.global [%0], [%1], 16;\n"
                 :: "r"(smem_dst), "l"(gsrc));
}

// ---------------- fp16 GEMM: C = A @ W^T (+bias, opt relu, opt pair-mean) ----------
// Block tile 128(M) x 128(N) x 32(K halves); 8 warps of 32x64; m16n8k16 f16 MMA,
// fp32 accumulate; 4-stage cp.async ring; 2 CTAs per SM.
// A:[M,K] fp16 row-major, W:[N,K] fp16 row-major. OUTH: C is fp16 else fp32.
// MEAN=1: C row r gets 0.5*(out[2r]+out[2r+1]) via shfl across lane^4 (after RELU).
#define BM2 128
#define BN2 128
#define BK2 32
#define NTHR 256
#define SR 40                              // halves per smem row (80B, 16B aligned)
#define A_STG (BM2 * SR)                   // 5120 halves
#define STG_HALFS (2 * A_STG)              // 10240 halves = 20480 B
#define NSTAGE 4
#define SMEM_BYTES (NSTAGE * STG_HALFS * 2)    // 81920 B

template<int RELU, int MEAN, int OUTH>
__launch_bounds__(NTHR, 2)
__global__ void gemm_h(const __half* __restrict__ A, const __half* __restrict__ W,
                       const float* __restrict__ bias, void* __restrict__ Cv,
                       int K, int ldc, int rowmul, int rowadd)
{
    extern __shared__ __half smh[];

    const int tid  = threadIdx.x;
    const int warp = tid >> 5;
    const int lane = tid & 31;
    const int g    = lane >> 2;
    const int tg   = lane & 3;
    const int wm   = (warp & 3) * 32;
    const int wn   = (warp >> 2) * 64;
    const int mblk = blockIdx.y * BM2;
    const int nblk = blockIdx.x * BN2;

    uint32_t smem_base;
    {
        void* p = smh;
        smem_base = (uint32_t)__cvta_generic_to_shared(p);
    }

    float acc[2][8][4];
#pragma unroll
    for (int i = 0; i < 2; i++)
#pragma unroll
        for (int j = 0; j < 8; j++)
#pragma unroll
            for (int q = 0; q < 4; q++) acc[i][j][q] = 0.f;

    // one K-stage: A 128 rows x 4 16B-chunks + B same = 1024 chunks, 4/thread
    auto issue = [&](int st, int kb) {
        const int k0 = kb * BK2;
        const uint32_t stg = smem_base + (uint32_t)(st * STG_HALFS) * 2u;
#pragma unroll
        for (int i = 0; i < 2; i++) {
            const int c  = tid + i * NTHR;      // 0..511
            const int m  = c >> 2;              // 0..127
            const int kc = (c & 3) * 8;         // halves
            cp_async16(stg + (uint32_t)(m * SR + kc) * 2u,
                       A + (size_t)(mblk + m) * K + k0 + kc);
            cp_async16(stg + (uint32_t)(A_STG + m * SR + kc) * 2u,
                       W + (size_t)(nblk + m) * K + k0 + kc);
        }
    };

    auto compute = [&](int st) {
        const __half* Ast = smh + st * STG_HALFS;
        const __half* Bst = Ast + A_STG;
#pragma unroll
        for (int ks = 0; ks < 2; ks++) {
            const int kb = ks * 16;
            uint32_t a[2][4];
#pragma unroll
            for (int i = 0; i < 2; i++) {
                const int m0 = wm + i * 16;
                a[i][0] = *(const uint32_t*)(Ast + (m0 + g    ) * SR + kb + 2 * tg);
                a[i][1] = *(const uint32_t*)(Ast + (m0 + g + 8) * SR + kb + 2 * tg);
                a[i][2] = *(const uint32_t*)(Ast + (m0 + g    ) * SR + kb + 2 * tg + 8);
                a[i][3] = *(const uint32_t*)(Ast + (m0 + g + 8) * SR + kb + 2 * tg + 8);
            }
            uint32_t b[8][2];
#pragma unroll
            for (int j = 0; j < 8; j++) {
                const int n0 = wn + j * 8;
                b[j][0] = *(const uint32_t*)(Bst + (n0 + g) * SR + kb + 2 * tg);
                b[j][1] = *(const uint32_t*)(Bst + (n0 + g) * SR + kb + 2 * tg + 8);
            }
#pragma unroll
            for (int i = 0; i < 2; i++)
#pragma unroll
                for (int j = 0; j < 8; j++)
                    asm volatile(
                        "mma.sync.aligned.m16n8k16.row.col.f32.f16.f16.f32 "
                        "{%0,%1,%2,%3}, {%4,%5,%6,%7}, {%8,%9}, {%0,%1,%2,%3};\n"
                        : "+f"(acc[i][j][0]), "+f"(acc[i][j][1]),
                          "+f"(acc[i][j][2]), "+f"(acc[i][j][3])
                        : "r"(a[i][0]), "r"(a[i][1]), "r"(a[i][2]), "r"(a[i][3]),
                          "r"(b[j][0]), "r"(b[j][1]));
        }
    };

    const int KT = K / BK2;

#pragma unroll
    for (int p = 0; p < NSTAGE - 1; p++) {
        if (p < KT) issue(p, p);
        asm volatile("cp.async.commit_group;\n" ::);
    }

    for (int kb = 0; kb < KT; kb++) {
        asm volatile("cp.async.wait_group %0;\n" :: "n"(NSTAGE - 2));
        __syncthreads();
        if (kb + NSTAGE - 1 < KT) issue((kb + NSTAGE - 1) % NSTAGE, kb + NSTAGE - 1);
        asm volatile("cp.async.commit_group;\n" ::);
        compute(kb % NSTAGE);
        __syncthreads();
    }

    float* Cf = (float*)Cv;
    __half* Ch = (__half*)Cv;

    // epilogue
#pragma unroll
    for (int i = 0; i < 2; i++) {
        const int row_a = mblk + wm + i * 16 + g;
        const int row_b = row_a + 8;
#pragma unroll
        for (int j = 0; j < 8; j++) {
            const int col = nblk + wn + j * 8 + 2 * tg;
            const float2 bv = *(const float2*)(bias + col);
            float o0 = acc[i][j][0] + bv.x;
            float o1 = acc[i][j][1] + bv.y;
            float o2 = acc[i][j][2] + bv.x;
            float o3 = acc[i][j][3] + bv.y;
            if (RELU) {
                o0 = fmaxf(o0, 0.f); o1 = fmaxf(o1, 0.f);
                o2 = fmaxf(o2, 0.f); o3 = fmaxf(o3, 0.f);
            }
            if (MEAN) {
                const float m0 = 0.5f * (o0 + __shfl_xor_sync(0xffffffffu, o0, 4));
                const float m1 = 0.5f * (o1 + __shfl_xor_sync(0xffffffffu, o1, 4));
                const float m2 = 0.5f * (o2 + __shfl_xor_sync(0xffffffffu, o2, 4));
                const float m3 = 0.5f * (o3 + __shfl_xor_sync(0xffffffffu, o3, 4));
                if ((g & 1) == 0) {
                    const size_t ra = (size_t)(row_a >> 1) * ldc + col;
                    const size_t rb = (size_t)(row_b >> 1) * ldc + col;
                    if (OUTH) {
                        *(__half2*)(Ch + ra) = __floats2half2_rn(m0, m1);
                        *(__half2*)(Ch + rb) = __floats2half2_rn(m2, m3);
                    } else {
                        *(float2*)(Cf + ra) = make_float2(m0, m1);
                        *(float2*)(Cf + rb) = make_float2(m2, m3);
                    }
                }
            } else {
                const size_t ca = (size_t)(rowmul * row_a + rowadd) * ldc + col;
                const size_t cb = (size_t)(rowmul * row_b + rowadd) * ldc + col;
                if (OUTH) {
                    *(__half2*)(Ch + ca) = __floats2half2_rn(o0, o1);
                    *(__half2*)(Ch + cb) = __floats2half2_rn(o2, o3);
                } else {
                    *(float2*)(Cf + ca) = make_float2(o0, o1);
                    *(float2*)(Cf + cb) = make_float2(o2, o3);
                }
            }
        }
    }
}

// ---------------- fp32 -> fp16 conversion ----------------
__global__ void cvt_kernel(const float* __restrict__ in, __half* __restrict__ out,
                           size_t n4)
{
    const size_t stride = (size_t)gridDim.x * blockDim.x;
    for (size_t i = (size_t)blockIdx.x * blockDim.x + threadIdx.x; i < n4; i += stride) {
        const float4 v = ((const float4*)in)[i];
        const __half2 h0 = __floats2half2_rn(v.x, v.y);
        const __half2 h1 = __floats2half2_rn(v.z, v.w);
        uint2 u;
        u.x = *(const uint32_t*)&h0;
        u.y = *(const uint32_t*)&h1;
        ((uint2*)out)[i] = u;
    }
}

// ---------------- LayerNorm, warp-per-row; fp32 in, fp32 or fp16 out ----------
__global__ void ln_kernel(const float* __restrict__ in, void* __restrict__ outv,
                          const float* __restrict__ g_e, const float* __restrict__ b_e,
                          const float* __restrict__ g_o, const float* __restrict__ b_o,
                          int relu, int outh)
{
    const int warp = threadIdx.x >> 5;
    const int lane = threadIdx.x & 31;
    const int row  = blockIdx.x * 8 + warp;
    const float* gg = (row & 1) ? g_o : g_e;
    const float* bb = (row & 1) ? b_o : b_e;

    const float4* rin = (const float4*)(in + (size_t)row * DIM);
    float4 v[8];
    float s = 0.f, q = 0.f;
#pragma unroll
    for (int i = 0; i < 8; i++) {
        v[i] = rin[lane + 32 * i];
        s += v[i].x + v[i].y + v[i].z + v[i].w;
        q += v[i].x*v[i].x + v[i].y*v[i].y + v[i].z*v[i].z + v[i].w*v[i].w;
    }
#pragma unroll
    for (int off = 16; off; off >>= 1) {
        s += __shfl_xor_sync(0xffffffffu, s, off);
        q += __shfl_xor_sync(0xffffffffu, q, off);
    }
    const float mu = s * (1.0f / DIM);
    const float var = q * (1.0f / DIM) - mu * mu;
    const float rs = rsqrtf(var + 1e-5f);

#pragma unroll
    for (int i = 0; i < 8; i++) {
        const int c4 = lane + 32 * i;
        const float4 gv = ((const float4*)gg)[c4];
        const float4 bv = ((const float4*)bb)[c4];
        float4 o;
        o.x = (v[i].x - mu) * rs * gv.x + bv.x;
        o.y = (v[i].y - mu) * rs * gv.y + bv.y;
        o.z = (v[i].z - mu) * rs * gv.z + bv.z;
        o.w = (v[i].w - mu) * rs * gv.w + bv.w;
        if (relu) {
            o.x = fmaxf(o.x, 0.f); o.y = fmaxf(o.y, 0.f);
            o.z = fmaxf(o.z, 0.f); o.w = fmaxf(o.w, 0.f);
        }
        if (outh) {
            const __half2 h0 = __floats2half2_rn(o.x, o.y);
            const __half2 h1 = __floats2half2_rn(o.z, o.w);
            uint2 u;
            u.x = *(const uint32_t*)&h0;
            u.y = *(const uint32_t*)&h1;
            ((uint2*)((__half*)outv + (size_t)row * DIM))[c4] = u;
        } else {
            ((float4*)((float*)outv + (size_t)row * DIM))[c4] = o;
        }
    }
}

__device__ __forceinline__ float lrelu(float v) { return v > 0.f ? v : 0.2f * v; }

// ---------------- gat1 fixup phase A: xp1[o] = dot(nodes[o>>11], W1[o&2047]) -------
__global__ void fixup1_xp(const __half* __restrict__ nodes_h, const float* __restrict__ W1,
                          float* __restrict__ xp1)
{
    const int w = blockIdx.x * 8 + (threadIdx.x >> 5);  // 0..2047
    const int lane = threadIdx.x & 31;
#pragma unroll
    for (int rep = 0; rep < 2; rep++) {
        const int o = w + rep * 2048;                   // 0..4095
        const int n = o >> 11, oc = o & 2047;
        const float* wr = W1 + (size_t)oc * DIM;
        const __half* nr = nodes_h + (size_t)n * DIM;
        float p = 0.f;
        for (int k = lane; k < DIM; k += 32) p += __half2float(nr[k]) * wr[k];
#pragma unroll
        for (int off = 16; off; off >>= 1) p += __shfl_xor_sync(0xffffffffu, p, off);
        if (lane == 0) xp1[o] = p;
    }
}

// ---------------- gat1 fixup phase B: attention mix, x1row01 + xmean1 row0 --------
__global__ void fixup1_fin(const float* __restrict__ xp1,
                           const float* __restrict__ as1, const float* __restrict__ ad1,
                           const float* __restrict__ b1, float* __restrict__ x1row01,
                           __half* __restrict__ xmean1h)
{
    __shared__ float sh_xp[2][2 * DIM];
    __shared__ float sh_sd[8];
    __shared__ float sh_w[8];
    const int tid = threadIdx.x, warp = tid >> 5, lane = tid & 31;

    for (int i = tid; i < 4096; i += 256) sh_xp[i >> 11][i & 2047] = xp1[i];
    __syncthreads();

    if (warp < 8) {
        const int n = warp >> 2, h = (warp >> 1) & 1, isd = warp & 1;
        const float* av = (isd ? ad1 : as1) + h * DIM;
        float p = 0.f;
        for (int k = lane; k < DIM; k += 32) p += sh_xp[n][h * DIM + k] * av[k];
#pragma unroll
        for (int off = 16; off; off >>= 1) p += __shfl_xor_sync(0xffffffffu, p, off);
        if (lane == 0) sh_sd[n * 4 + h * 2 + isd] = p;
    }
    __syncthreads();

    if (tid == 0) {
#pragma unroll
        for (int h = 0; h < 2; h++) {
            const float s0 = sh_sd[0*4 + h*2 + 0], d0 = sh_sd[0*4 + h*2 + 1];
            const float s1 = sh_sd[1*4 + h*2 + 0], d1 = sh_sd[1*4 + h*2 + 1];
            const float e00 = lrelu(s0 + d0), e10 = lrelu(s1 + d0);
            const float e11 = lrelu(s1 + d1), e01 = lrelu(s0 + d1);
            const float m0 = fmaxf(e00, e10);
            const float w00 = expf(e00 - m0), w10 = expf(e10 - m0);
            const float inv0 = 1.f / (w00 + w10);
            const float m1 = fmaxf(e11, e01);
            const float w11 = expf(e11 - m1), w01 = expf(e01 - m1);
            const float inv1 = 1.f / (w11 + w01);
            sh_w[h*4+0] = w00 * inv0;
            sh_w[h*4+1] = w10 * inv0;
            sh_w[h*4+2] = w11 * inv1;
            sh_w[h*4+3] = w01 * inv1;
        }
    }
    __syncthreads();

    for (int idx = tid; idx < 2 * DIM; idx += 256) {
        const int h = idx >> 10;
        const float o0 = sh_w[h*4+0] * sh_xp[0][idx] + sh_w[h*4+1] * sh_xp[1][idx];
        const float o1 = sh_w[h*4+2] * sh_xp[1][idx] + sh_w[h*4+3] * sh_xp[0][idx];
        const float r0 = fmaxf(o0 + b1[idx], 0.f);
        const float r1 = fmaxf(o1 + b1[idx], 0.f);
        x1row01[idx]           = r0;
        x1row01[2 * DIM + idx] = r1;
        xmean1h[idx] = __float2half_rn(0.5f * (r0 + r1));
    }
}

// ---------------- gat2 fixup phase A: xp2[o] = dot(x1row01[o>>10], W2[o&1023]) -----
__global__ void fixup2_xp(const float* __restrict__ x1row01, const float* __restrict__ W2,
                          float* __restrict__ xp2)
{
    const int o = blockIdx.x * 8 + (threadIdx.x >> 5);  // 0..2047
    const int lane = threadIdx.x & 31;
    const int n = o >> 10, oc = o & 1023;
    const float* wr = W2 + (size_t)oc * (2 * DIM);
    const float* xr = x1row01 + (size_t)n * (2 * DIM);
    float p = 0.f;
    for (int k = lane; k < 2 * DIM; k += 32) p += xr[k] * wr[k];
#pragma unroll
    for (int off = 16; off; off >>= 1) p += __shfl_xor_sync(0xffffffffu, p, off);
    if (lane == 0) xp2[o] = p;
}

// ---------------- gat2 fixup phase B: exact xm row 0 (fp16) ----------------
__global__ void fixup2_fin(const float* __restrict__ xp2,
                           const float* __restrict__ as2, const float* __restrict__ ad2,
                           const float* __restrict__ b2, __half* __restrict__ xm_h)
{
    __shared__ float sh_xp[2][DIM];
    __shared__ float sh_sd[4];
    __shared__ float sh_w[4];
    const int tid = threadIdx.x, warp = tid >> 5, lane = tid & 31;

    for (int i = tid; i < 2 * DIM; i += 256) sh_xp[i >> 10][i & 1023] = xp2[i];
    __syncthreads();

    if (warp < 4) {
        const int n = warp >> 1, isd = warp & 1;
        const float* av = isd ? ad2 : as2;
        float p = 0.f;
        for (int k = lane; k < DIM; k += 32) p += sh_xp[n][k] * av[k];
#pragma unroll
        for (int off = 16; off; off >>= 1) p += __shfl_xor_sync(0xffffffffu, p, off);
        if (lane == 0) sh_sd[n * 2 + isd] = p;
    }
    __syncthreads();

    if (tid == 0) {
        const float s0 = sh_sd[0], d0 = sh_sd[1], s1 = sh_sd[2], d1 = sh_sd[3];
        const float e00 = lrelu(s0 + d0), e10 = lrelu(s1 + d0);
        const float e11 = lrelu(s1 + d1), e01 = lrelu(s0 + d1);
        const float m0 = fmaxf(e00, e10);
        const float w00 = expf(e00 - m0), w10 = expf(e10 - m0);
        const float inv0 = 1.f / (w00 + w10);
        const float m1 = fmaxf(e11, e01);
        const float w11 = expf(e11 - m1), w01 = expf(e01 - m1);
        const float inv1 = 1.f / (w11 + w01);
        sh_w[0] = w00 * inv0; sh_w[1] = w10 * inv0;
        sh_w[2] = w11 * inv1; sh_w[3] = w01 * inv1;
    }
    __syncthreads();

    for (int idx = tid; idx < DIM; idx += 256) {
        const float o0 = sh_w[0] * sh_xp[0][idx] + sh_w[1] * sh_xp[1][idx] + b2[idx];
        const float o1 = sh_w[2] * sh_xp[1][idx] + sh_w[3] * sh_xp[0][idx] + b2[idx];
        xm_h[idx] = __float2half_rn(0.5f * (o0 + o1));
    }
}

// ---------------- launch ----------------
extern "C" void kernel_launch(void* const* d_in, const int* in_sizes, int n_in,
                              void* d_out, int out_size)
{
    const float* audio = (const float*)d_in[0];
    const float* text  = (const float*)d_in[1];
    const float* Wa    = (const float*)d_in[2];
    const float* ba    = (const float*)d_in[3];
    const float* lna_g = (const float*)d_in[4];
    const float* lna_b = (const float*)d_in[5];
    const float* Wt    = (const float*)d_in[6];
    const float* bt    = (const float*)d_in[7];
    const float* lnt_g = (const float*)d_in[8];
    const float* lnt_b = (const float*)d_in[9];
    const float* W1    = (const float*)d_in[10];
    const float* as1   = (const float*)d_in[11];
    const float* ad1   = (const float*)d_in[12];
    const float* b1    = (const float*)d_in[13];
    const float* W2    = (const float*)d_in[14];
    const float* as2   = (const float*)d_in[15];
    const float* ad2   = (const float*)d_in[16];
    const float* b2    = (const float*)d_in[17];
    const float* Wf    = (const float*)d_in[18];
    const float* bf    = (const float*)d_in[19];
    const float* lnf_g = (const float*)d_in[20];
    const float* lnf_b = (const float*)d_in[21];

    __half *audio_h, *text_h, *Wa_h, *Wt_h, *W1_h, *W2_h, *Wf_h;
    __half *nodes_h, *xmean1h, *xm_h;
    float *pre, *x1row01, *xp1, *xp2, *fcb;
    cudaGetSymbolAddress((void**)&audio_h, g_audio_h);
    cudaGetSymbolAddress((void**)&text_h,  g_text_h);
    cudaGetSymbolAddress((void**)&Wa_h,    g_Wa_h);
    cudaGetSymbolAddress((void**)&Wt_h,    g_Wt_h);
    cudaGetSymbolAddress((void**)&W1_h,    g_W1_h);
    cudaGetSymbolAddress((void**)&W2_h,    g_W2_h);
    cudaGetSymbolAddress((void**)&Wf_h,    g_Wf_h);
    cudaGetSymbolAddress((void**)&pre,     g_pre);
    cudaGetSymbolAddress((void**)&nodes_h, g_nodes_h);
    cudaGetSymbolAddress((void**)&xmean1h, g_xmean1h);
    cudaGetSymbolAddress((void**)&x1row01, g_x1row01);
    cudaGetSymbolAddress((void**)&xp1,     g_xp1);
    cudaGetSymbolAddress((void**)&xp2,     g_xp2);
    cudaGetSymbolAddress((void**)&xm_h,    g_xm_h);
    cudaGetSymbolAddress((void**)&fcb,     g_fcb);

    cudaFuncSetAttribute(gemm_h<0,0,0>, cudaFuncAttributeMaxDynamicSharedMemorySize, SMEM_BYTES);
    cudaFuncSetAttribute(gemm_h<1,1,1>, cudaFuncAttributeMaxDynamicSharedMemorySize, SMEM_BYTES);
    cudaFuncSetAttribute(gemm_h<0,0,1>, cudaFuncAttributeMaxDynamicSharedMemorySize, SMEM_BYTES);

    const size_t nBD4 = (size_t)BATCH * DIM / 4;
    const size_t nDD4 = (size_t)DIM * DIM / 4;

    // fp32 -> fp16 operand conversion
    cvt_kernel<<<4096, 256>>>(audio, audio_h, nBD4);
    cvt_kernel<<<4096, 256>>>(text,  text_h,  nBD4);
    cvt_kernel<<<2048, 256>>>(Wa, Wa_h, nDD4);
    cvt_kernel<<<2048, 256>>>(Wt, Wt_h, nDD4);
    cvt_kernel<<<4096, 256>>>(W1, W1_h, 2 * nDD4);
    cvt_kernel<<<4096, 256>>>(W2, W2_h, 2 * nDD4);
    cvt_kernel<<<2048, 256>>>(Wf, Wf_h, nDD4);

    dim3 blk(NTHR);

    // proj_audio / proj_text -> interleaved pre-LN rows (fp32 out)
    gemm_h<0,0,0><<<dim3(8, 128), blk, SMEM_BYTES>>>(audio_h, Wa_h, ba, pre, 1024, 1024, 2, 0);
    gemm_h<0,0,0><<<dim3(8, 128), blk, SMEM_BYTES>>>(text_h,  Wt_h, bt, pre, 1024, 1024, 2, 1);
    // LN + relu -> fp16 nodes
    ln_kernel<<<NNODES / 8, 256>>>(pre, nodes_h, lna_g, lna_b, lnt_g, lnt_b, 1, 1);
    // gat1 + relu + fused pair-mean -> fp16 xmean1 [BATCH, 2*DIM]
    gemm_h<1,1,1><<<dim3(16, 256), blk, SMEM_BYTES>>>(nodes_h, W1_h, b1, xmean1h, 1024, 2048, 1, 0);
    // parallel attention fixup for rows 0,1 (patches xmean1 row 0 before gat2)
    fixup1_xp<<<256, 256>>>(nodes_h, W1, xp1);
    fixup1_fin<<<1, 256>>>(xp1, as1, ad1, b1, x1row01, xmean1h);
    // gat2 on pre-meaned input (affine => mean commutes) -> fp16 xm
    gemm_h<0,0,1><<<dim3(8, 128), blk, SMEM_BYTES>>>(xmean1h, W2_h, b2, xm_h, 2048, 1024, 1, 0);
    // parallel exact xm row 0
    fixup2_xp<<<256, 256>>>(x1row01, W2, xp2);
    fixup2_fin<<<1, 256>>>(xp2, as2, ad2, b2, xm_h);
    // fc -> fp32 fcb
    gemm_h<0,0,0><<<dim3(8, 128), blk, SMEM_BYTES>>>(xm_h, Wf_h, bf, fcb, 1024, 1024, 1, 0);
    // final LN -> fp32 out
    ln_kernel<<<BATCH / 8, 256>>>(fcb, (float*)d_out, lnf_g, lnf_b, lnf_g, lnf_b, 0, 0);
}

// round 16
// speedup vs baseline: 2.8653x; 1.0222x over previous
#include <cuda_runtime.h>
#include <cuda_fp16.h>
#include <cstdint>
#include <cstddef>
#include <math.h>

#define BATCH 16384
#define DIM   1024
#define NNODES (2*BATCH)

// ---------------- scratch (static device memory: allowed) ----------------
__device__ __half g_Wa_h   [(size_t)DIM * DIM];
__device__ __half g_Wt_h   [(size_t)DIM * DIM];
__device__ __half g_W1_h   [(size_t)2 * DIM * DIM];
__device__ __half g_W2_h   [(size_t)DIM * 2 * DIM];
__device__ __half g_Wf_h   [(size_t)DIM * DIM];
__device__ float  g_pre    [(size_t)NNODES * DIM];     // proj out pre-LN (interleaved)
__device__ __half g_nodes_h[(size_t)NNODES * DIM];     // post LN+relu (fp16)
__device__ __half g_xmean1h[(size_t)BATCH * 2 * DIM];  // pair-mean of gat1 out (fp16)
__device__ float  g_x1row01[2 * 2 * DIM];              // exact x1 rows 0,1 (fp32)
__device__ float  g_xp1    [2 * 2 * DIM];              // gat1 xp for rows 0,1
__device__ float  g_xp2    [2 * DIM];                  // gat2 xp for rows 0,1
__device__ __half g_xm_h   [(size_t)BATCH * DIM];      // gat2 out (fp16)
__device__ float  g_fcb    [(size_t)BATCH * DIM];      // fc out pre-LN (fp32)

__device__ __forceinline__ void cp_async16(uint32_t smem_dst, const void* gsrc) {
    asm volatile("cp.async.cg.shared.global [%0], [%1], 16;\n"
                 :: "r"(smem_dst), "l"(gsrc));
}

// =====================================================================
// fp16 GEMM (A fp16): C = A @ W^T (+bias, opt relu, opt pair-mean)
// Block 128x128xK32(halves); 8 warps of 32x64; m16n8k16 f16 MMA, fp32 acc;
// 4-stage cp.async ring; 2 CTAs/SM. OUTH: C fp16 else fp32.
// =====================================================================
#define BM2 128
#define BN2 128
#define BK2 32
#define NTHR 256
#define SR 40                              // halves per smem row (80B)
#define A_STG (BM2 * SR)                   // 5120 halves
#define STG_HALFS (2 * A_STG)              // 20480 B
#define NSTAGE 4
#define SMEM_BYTES (NSTAGE * STG_HALFS * 2)    // 81920 B

template<int RELU, int MEAN, int OUTH>
__launch_bounds__(NTHR, 2)
__global__ void gemm_h(const __half* __restrict__ A, const __half* __restrict__ W,
                       const float* __restrict__ bias, void* __restrict__ Cv,
                       int K, int ldc, int rowmul, int rowadd)
{
    extern __shared__ __half smh[];

    const int tid  = threadIdx.x;
    const int warp = tid >> 5;
    const int lane = tid & 31;
    const int g    = lane >> 2;
    const int tg   = lane & 3;
    const int wm   = (warp & 3) * 32;
    const int wn   = (warp >> 2) * 64;
    const int mblk = blockIdx.y * BM2;
    const int nblk = blockIdx.x * BN2;

    uint32_t smem_base;
    {
        void* p = smh;
        smem_base = (uint32_t)__cvta_generic_to_shared(p);
    }

    float acc[2][8][4];
#pragma unroll
    for (int i = 0; i < 2; i++)
#pragma unroll
        for (int j = 0; j < 8; j++)
#pragma unroll
            for (int q = 0; q < 4; q++) acc[i][j][q] = 0.f;

    auto issue = [&](int st, int kb) {
        const int k0 = kb * BK2;
        const uint32_t stg = smem_base + (uint32_t)(st * STG_HALFS) * 2u;
#pragma unroll
        for (int i = 0; i < 2; i++) {
            const int c  = tid + i * NTHR;
            const int m  = c >> 2;
            const int kc = (c & 3) * 8;
            cp_async16(stg + (uint32_t)(m * SR + kc) * 2u,
                       A + (size_t)(mblk + m) * K + k0 + kc);
            cp_async16(stg + (uint32_t)(A_STG + m * SR + kc) * 2u,
                       W + (size_t)(nblk + m) * K + k0 + kc);
        }
    };

    auto compute = [&](int st) {
        const __half* Ast = smh + st * STG_HALFS;
        const __half* Bst = Ast + A_STG;
#pragma unroll
        for (int ks = 0; ks < 2; ks++) {
            const int kb = ks * 16;
            uint32_t a[2][4];
#pragma unroll
            for (int i = 0; i < 2; i++) {
                const int m0 = wm + i * 16;
                a[i][0] = *(const uint32_t*)(Ast + (m0 + g    ) * SR + kb + 2 * tg);
                a[i][1] = *(const uint32_t*)(Ast + (m0 + g + 8) * SR + kb + 2 * tg);
                a[i][2] = *(const uint32_t*)(Ast + (m0 + g    ) * SR + kb + 2 * tg + 8);
                a[i][3] = *(const uint32_t*)(Ast + (m0 + g + 8) * SR + kb + 2 * tg + 8);
            }
            uint32_t b[8][2];
#pragma unroll
            for (int j = 0; j < 8; j++) {
                const int n0 = wn + j * 8;
                b[j][0] = *(const uint32_t*)(Bst + (n0 + g) * SR + kb + 2 * tg);
                b[j][1] = *(const uint32_t*)(Bst + (n0 + g) * SR + kb + 2 * tg + 8);
            }
#pragma unroll
            for (int i = 0; i < 2; i++)
#pragma unroll
                for (int j = 0; j < 8; j++)
                    asm volatile(
                        "mma.sync.aligned.m16n8k16.row.col.f32.f16.f16.f32 "
                        "{%0,%1,%2,%3}, {%4,%5,%6,%7}, {%8,%9}, {%0,%1,%2,%3};\n"
                        : "+f"(acc[i][j][0]), "+f"(acc[i][j][1]),
                          "+f"(acc[i][j][2]), "+f"(acc[i][j][3])
                        : "r"(a[i][0]), "r"(a[i][1]), "r"(a[i][2]), "r"(a[i][3]),
                          "r"(b[j][0]), "r"(b[j][1]));
        }
    };

    const int KT = K / BK2;

#pragma unroll
    for (int p = 0; p < NSTAGE - 1; p++) {
        if (p < KT) issue(p, p);
        asm volatile("cp.async.commit_group;\n" ::);
    }

    for (int kb = 0; kb < KT; kb++) {
        asm volatile("cp.async.wait_group %0;\n" :: "n"(NSTAGE - 2));
        __syncthreads();
        if (kb + NSTAGE - 1 < KT) issue((kb + NSTAGE - 1) % NSTAGE, kb + NSTAGE - 1);
        asm volatile("cp.async.commit_group;\n" ::);
        compute(kb % NSTAGE);
        __syncthreads();
    }

    float* Cf = (float*)Cv;
    __half* Ch = (__half*)Cv;

#pragma unroll
    for (int i = 0; i < 2; i++) {
        const int row_a = mblk + wm + i * 16 + g;
        const int row_b = row_a + 8;
#pragma unroll
        for (int j = 0; j < 8; j++) {
            const int col = nblk + wn + j * 8 + 2 * tg;
            const float2 bv = *(const float2*)(bias + col);
            float o0 = acc[i][j][0] + bv.x;
            float o1 = acc[i][j][1] + bv.y;
            float o2 = acc[i][j][2] + bv.x;
            float o3 = acc[i][j][3] + bv.y;
            if (RELU) {
                o0 = fmaxf(o0, 0.f); o1 = fmaxf(o1, 0.f);
                o2 = fmaxf(o2, 0.f); o3 = fmaxf(o3, 0.f);
            }
            if (MEAN) {
                const float m0 = 0.5f * (o0 + __shfl_xor_sync(0xffffffffu, o0, 4));
                const float m1 = 0.5f * (o1 + __shfl_xor_sync(0xffffffffu, o1, 4));
                const float m2 = 0.5f * (o2 + __shfl_xor_sync(0xffffffffu, o2, 4));
                const float m3 = 0.5f * (o3 + __shfl_xor_sync(0xffffffffu, o3, 4));
                if ((g & 1) == 0) {
                    const size_t ra = (size_t)(row_a >> 1) * ldc + col;
                    const size_t rb = (size_t)(row_b >> 1) * ldc + col;
                    if (OUTH) {
                        *(__half2*)(Ch + ra) = __floats2half2_rn(m0, m1);
                        *(__half2*)(Ch + rb) = __floats2half2_rn(m2, m3);
                    } else {
                        *(float2*)(Cf + ra) = make_float2(m0, m1);
                        *(float2*)(Cf + rb) = make_float2(m2, m3);
                    }
                }
            } else {
                const size_t ca = (size_t)(rowmul * row_a + rowadd) * ldc + col;
                const size_t cb = (size_t)(rowmul * row_b + rowadd) * ldc + col;
                if (OUTH) {
                    *(__half2*)(Ch + ca) = __floats2half2_rn(o0, o1);
                    *(__half2*)(Ch + cb) = __floats2half2_rn(o2, o3);
                } else {
                    *(float2*)(Cf + ca) = make_float2(o0, o1);
                    *(float2*)(Cf + cb) = make_float2(o2, o3);
                }
            }
        }
    }
}

// =====================================================================
// fp32-A GEMM: A fp32 (converted post-LDS), W fp16. Used by proj layers.
// Same tile/fragments; 3-stage ring (bigger stages); 2 CTAs/SM.
// =====================================================================
#define ASRF 40                                // floats per A smem row (160B)
#define A_STGF_BYTES (BM2 * ASRF * 4)          // 20480 B
#define B_STGH_BYTES (BM2 * SR * 2)            // 10240 B
#define STGA_BYTES (A_STGF_BYTES + B_STGH_BYTES)   // 30720 B
#define NSTAGEA 3
#define SMEM_BYTES_A (NSTAGEA * STGA_BYTES)    // 92160 B

__launch_bounds__(NTHR, 2)
__global__ void gemm_ha(const float* __restrict__ A, const __half* __restrict__ W,
                        const float* __restrict__ bias, float* __restrict__ C,
                        int K, int ldc, int rowmul, int rowadd)
{
    extern __shared__ char smc[];

    const int tid  = threadIdx.x;
    const int warp = tid >> 5;
    const int lane = tid & 31;
    const int g    = lane >> 2;
    const int tg   = lane & 3;
    const int wm   = (warp & 3) * 32;
    const int wn   = (warp >> 2) * 64;
    const int mblk = blockIdx.y * BM2;
    const int nblk = blockIdx.x * BN2;

    uint32_t smem_base;
    {
        void* p = smc;
        smem_base = (uint32_t)__cvta_generic_to_shared(p);
    }

    float acc[2][8][4];
#pragma unroll
    for (int i = 0; i < 2; i++)
#pragma unroll
        for (int j = 0; j < 8; j++)
#pragma unroll
            for (int q = 0; q < 4; q++) acc[i][j][q] = 0.f;

    // A: 128 rows x 8 16B-chunks (32 floats) = 1024 chunks; B: 128 x 4 = 512
    auto issue = [&](int st, int kb) {
        const int k0 = kb * BK2;
        const uint32_t stg = smem_base + (uint32_t)(st * STGA_BYTES);
#pragma unroll
        for (int i = 0; i < 4; i++) {
            const int c  = tid + i * NTHR;      // 0..1023
            const int m  = c >> 3;
            const int kc = (c & 7) * 4;         // floats
            cp_async16(stg + (uint32_t)(m * ASRF + kc) * 4u,
                       A + (size_t)(mblk + m) * K + k0 + kc);
        }
#pragma unroll
        for (int i = 0; i < 2; i++) {
            const int c  = tid + i * NTHR;      // 0..511
            const int m  = c >> 2;
            const int kc = (c & 3) * 8;         // halves
            cp_async16(stg + A_STGF_BYTES + (uint32_t)(m * SR + kc) * 2u,
                       W + (size_t)(nblk + m) * K + k0 + kc);
        }
    };

    auto compute = [&](int st) {
        const float*  Ast = (const float*)(smc + st * STGA_BYTES);
        const __half* Bst = (const __half*)(smc + st * STGA_BYTES + A_STGF_BYTES);
#pragma unroll
        for (int ks = 0; ks < 2; ks++) {
            const int kb = ks * 16;
            uint32_t a[2][4];
#pragma unroll
            for (int i = 0; i < 2; i++) {
                const int m0 = wm + i * 16;
                const float2 p00 = *(const float2*)(Ast + (m0 + g    ) * ASRF + kb + 2 * tg);
                const float2 p10 = *(const float2*)(Ast + (m0 + g + 8) * ASRF + kb + 2 * tg);
                const float2 p01 = *(const float2*)(Ast + (m0 + g    ) * ASRF + kb + 2 * tg + 8);
                const float2 p11 = *(const float2*)(Ast + (m0 + g + 8) * ASRF + kb + 2 * tg + 8);
                const __half2 h00 = __floats2half2_rn(p00.x, p00.y);
                const __half2 h10 = __floats2half2_rn(p10.x, p10.y);
                const __half2 h01 = __floats2half2_rn(p01.x, p01.y);
                const __half2 h11 = __floats2half2_rn(p11.x, p11.y);
                a[i][0] = *(const uint32_t*)&h00;
                a[i][1] = *(const uint32_t*)&h10;
                a[i][2] = *(const uint32_t*)&h01;
                a[i][3] = *(const uint32_t*)&h11;
            }
            uint32_t b[8][2];
#pragma unroll
            for (int j = 0; j < 8; j++) {
                const int n0 = wn + j * 8;
                b[j][0] = *(const uint32_t*)(Bst + (n0 + g) * SR + kb + 2 * tg);
                b[j][1] = *(const uint32_t*)(Bst + (n0 + g) * SR + kb + 2 * tg + 8);
            }
#pragma unroll
            for (int i = 0; i < 2; i++)
#pragma unroll
                for (int j = 0; j < 8; j++)
                    asm volatile(
                        "mma.sync.aligned.m16n8k16.row.col.f32.f16.f16.f32 "
                        "{%0,%1,%2,%3}, {%4,%5,%6,%7}, {%8,%9}, {%0,%1,%2,%3};\n"
                        : "+f"(acc[i][j][0]), "+f"(acc[i][j][1]),
                          "+f"(acc[i][j][2]), "+f"(acc[i][j][3])
                        : "r"(a[i][0]), "r"(a[i][1]), "r"(a[i][2]), "r"(a[i][3]),
                          "r"(b[j][0]), "r"(b[j][1]));
        }
    };

    const int KT = K / BK2;

#pragma unroll
    for (int p = 0; p < NSTAGEA - 1; p++) {
        if (p < KT) issue(p, p);
        asm volatile("cp.async.commit_group;\n" ::);
    }

    for (int kb = 0; kb < KT; kb++) {
        asm volatile("cp.async.wait_group %0;\n" :: "n"(NSTAGEA - 2));
        __syncthreads();
        if (kb + NSTAGEA - 1 < KT) issue((kb + NSTAGEA - 1) % NSTAGEA, kb + NSTAGEA - 1);
        asm volatile("cp.async.commit_group;\n" ::);
        compute(kb % NSTAGEA);
        __syncthreads();
    }

#pragma unroll
    for (int i = 0; i < 2; i++) {
        const int row_a = mblk + wm + i * 16 + g;
        const int row_b = row_a + 8;
#pragma unroll
        for (int j = 0; j < 8; j++) {
            const int col = nblk + wn + j * 8 + 2 * tg;
            const float2 bv = *(const float2*)(bias + col);
            const float o0 = acc[i][j][0] + bv.x;
            const float o1 = acc[i][j][1] + bv.y;
            const float o2 = acc[i][j][2] + bv.x;
            const float o3 = acc[i][j][3] + bv.y;
            const size_t ca = (size_t)(rowmul * row_a + rowadd) * ldc + col;
            const size_t cb = (size_t)(rowmul * row_b + rowadd) * ldc + col;
            *(float2*)(C + ca) = make_float2(o0, o1);
            *(float2*)(C + cb) = make_float2(o2, o3);
        }
    }
}

// ---------------- fp32 -> fp16 conversion (weights) ----------------
__global__ void cvt_kernel(const float* __restrict__ in, __half* __restrict__ out,
                           size_t n4)
{
    const size_t stride = (size_t)gridDim.x * blockDim.x;
    for (size_t i = (size_t)blockIdx.x * blockDim.x + threadIdx.x; i < n4; i += stride) {
        const float4 v = ((const float4*)in)[i];
        const __half2 h0 = __floats2half2_rn(v.x, v.y);
        const __half2 h1 = __floats2half2_rn(v.z, v.w);
        uint2 u;
        u.x = *(const uint32_t*)&h0;
        u.y = *(const uint32_t*)&h1;
        ((uint2*)out)[i] = u;
    }
}

// ---------------- LayerNorm, warp-per-row; fp32 in, fp32 or fp16 out ----------
__global__ void ln_kernel(const float* __restrict__ in, void* __restrict__ outv,
                          const float* __restrict__ g_e, const float* __restrict__ b_e,
                          const float* __restrict__ g_o, const float* __restrict__ b_o,
                          int relu, int outh)
{
    const int warp = threadIdx.x >> 5;
    const int lane = threadIdx.x & 31;
    const int row  = blockIdx.x * 8 + warp;
    const float* gg = (row & 1) ? g_o : g_e;
    const float* bb = (row & 1) ? b_o : b_e;

    const float4* rin = (const float4*)(in + (size_t)row * DIM);
    float4 v[8];
    float s = 0.f, q = 0.f;
#pragma unroll
    for (int i = 0; i < 8; i++) {
        v[i] = rin[lane + 32 * i];
        s += v[i].x + v[i].y + v[i].z + v[i].w;
        q += v[i].x*v[i].x + v[i].y*v[i].y + v[i].z*v[i].z + v[i].w*v[i].w;
    }
#pragma unroll
    for (int off = 16; off; off >>= 1) {
        s += __shfl_xor_sync(0xffffffffu, s, off);
        q += __shfl_xor_sync(0xffffffffu, q, off);
    }
    const float mu = s * (1.0f / DIM);
    const float var = q * (1.0f / DIM) - mu * mu;
    const float rs = rsqrtf(var + 1e-5f);

#pragma unroll
    for (int i = 0; i < 8; i++) {
        const int c4 = lane + 32 * i;
        const float4 gv = ((const float4*)gg)[c4];
        const float4 bv = ((const float4*)bb)[c4];
        float4 o;
        o.x = (v[i].x - mu) * rs * gv.x + bv.x;
        o.y = (v[i].y - mu) * rs * gv.y + bv.y;
        o.z = (v[i].z - mu) * rs * gv.z + bv.z;
        o.w = (v[i].w - mu) * rs * gv.w + bv.w;
        if (relu) {
            o.x = fmaxf(o.x, 0.f); o.y = fmaxf(o.y, 0.f);
            o.z = fmaxf(o.z, 0.f); o.w = fmaxf(o.w, 0.f);
        }
        if (outh) {
            const __half2 h0 = __floats2half2_rn(o.x, o.y);
            const __half2 h1 = __floats2half2_rn(o.z, o.w);
            uint2 u;
            u.x = *(const uint32_t*)&h0;
            u.y = *(const uint32_t*)&h1;
            ((uint2*)((__half*)outv + (size_t)row * DIM))[c4] = u;
        } else {
            ((float4*)((float*)outv + (size_t)row * DIM))[c4] = o;
        }
    }
}

__device__ __forceinline__ float lrelu(float v) { return v > 0.f ? v : 0.2f * v; }

// ---------------- gat1 fixup phase A ----------------
__global__ void fixup1_xp(const __half* __restrict__ nodes_h, const float* __restrict__ W1,
                          float* __restrict__ xp1)
{
    const int w = blockIdx.x * 8 + (threadIdx.x >> 5);
    const int lane = threadIdx.x & 31;
#pragma unroll
    for (int rep = 0; rep < 2; rep++) {
        const int o = w + rep * 2048;
        const int n = o >> 11, oc = o & 2047;
        const float* wr = W1 + (size_t)oc * DIM;
        const __half* nr = nodes_h + (size_t)n * DIM;
        float p = 0.f;
        for (int k = lane; k < DIM; k += 32) p += __half2float(nr[k]) * wr[k];
#pragma unroll
        for (int off = 16; off; off >>= 1) p += __shfl_xor_sync(0xffffffffu, p, off);
        if (lane == 0) xp1[o] = p;
    }
}

// ---------------- gat1 fixup phase B ----------------
__global__ void fixup1_fin(const float* __restrict__ xp1,
                           const float* __restrict__ as1, const float* __restrict__ ad1,
                           const float* __restrict__ b1, float* __restrict__ x1row01,
                           __half* __restrict__ xmean1h)
{
    __shared__ float sh_xp[2][2 * DIM];
    __shared__ float sh_sd[8];
    __shared__ float sh_w[8];
    const int tid = threadIdx.x, warp = tid >> 5, lane = tid & 31;

    for (int i = tid; i < 4096; i += 256) sh_xp[i >> 11][i & 2047] = xp1[i];
    __syncthreads();

    if (warp < 8) {
        const int n = warp >> 2, h = (warp >> 1) & 1, isd = warp & 1;
        const float* av = (isd ? ad1 : as1) + h * DIM;
        float p = 0.f;
        for (int k = lane; k < DIM; k += 32) p += sh_xp[n][h * DIM + k] * av[k];
#pragma unroll
        for (int off = 16; off; off >>= 1) p += __shfl_xor_sync(0xffffffffu, p, off);
        if (lane == 0) sh_sd[n * 4 + h * 2 + isd] = p;
    }
    __syncthreads();

    if (tid == 0) {
#pragma unroll
        for (int h = 0; h < 2; h++) {
            const float s0 = sh_sd[0*4 + h*2 + 0], d0 = sh_sd[0*4 + h*2 + 1];
            const float s1 = sh_sd[1*4 + h*2 + 0], d1 = sh_sd[1*4 + h*2 + 1];
            const float e00 = lrelu(s0 + d0), e10 = lrelu(s1 + d0);
            const float e11 = lrelu(s1 + d1), e01 = lrelu(s0 + d1);
            const float m0 = fmaxf(e00, e10);
            const float w00 = expf(e00 - m0), w10 = expf(e10 - m0);
            const float inv0 = 1.f / (w00 + w10);
            const float m1 = fmaxf(e11, e01);
            const float w11 = expf(e11 - m1), w01 = expf(e01 - m1);
            const float inv1 = 1.f / (w11 + w01);
            sh_w[h*4+0] = w00 * inv0;
            sh_w[h*4+1] = w10 * inv0;
            sh_w[h*4+2] = w11 * inv1;
            sh_w[h*4+3] = w01 * inv1;
        }
    }
    __syncthreads();

    for (int idx = tid; idx < 2 * DIM; idx += 256) {
        const int h = idx >> 10;
        const float o0 = sh_w[h*4+0] * sh_xp[0][idx] + sh_w[h*4+1] * sh_xp[1][idx];
        const float o1 = sh_w[h*4+2] * sh_xp[1][idx] + sh_w[h*4+3] * sh_xp[0][idx];
        const float r0 = fmaxf(o0 + b1[idx], 0.f);
        const float r1 = fmaxf(o1 + b1[idx], 0.f);
        x1row01[idx]           = r0;
        x1row01[2 * DIM + idx] = r1;
        xmean1h[idx] = __float2half_rn(0.5f * (r0 + r1));
    }
}

// ---------------- gat2 fixup phase A ----------------
__global__ void fixup2_xp(const float* __restrict__ x1row01, const float* __restrict__ W2,
                          float* __restrict__ xp2)
{
    const int o = blockIdx.x * 8 + (threadIdx.x >> 5);
    const int lane = threadIdx.x & 31;
    const int n = o >> 10, oc = o & 1023;
    const float* wr = W2 + (size_t)oc * (2 * DIM);
    const float* xr = x1row01 + (size_t)n * (2 * DIM);
    float p = 0.f;
    for (int k = lane; k < 2 * DIM; k += 32) p += xr[k] * wr[k];
#pragma unroll
    for (int off = 16; off; off >>= 1) p += __shfl_xor_sync(0xffffffffu, p, off);
    if (lane == 0) xp2[o] = p;
}

// ---------------- gat2 fixup phase B ----------------
__global__ void fixup2_fin(const float* __restrict__ xp2,
                           const float* __restrict__ as2, const float* __restrict__ ad2,
                           const float* __restrict__ b2, __half* __restrict__ xm_h)
{
    __shared__ float sh_xp[2][DIM];
    __shared__ float sh_sd[4];
    __shared__ float sh_w[4];
    const int tid = threadIdx.x, warp = tid >> 5, lane = tid & 31;

    for (int i = tid; i < 2 * DIM; i += 256) sh_xp[i >> 10][i & 1023] = xp2[i];
    __syncthreads();

    if (warp < 4) {
        const int n = warp >> 1, isd = warp & 1;
        const float* av = isd ? ad2 : as2;
        float p = 0.f;
        for (int k = lane; k < DIM; k += 32) p += sh_xp[n][k] * av[k];
#pragma unroll
        for (int off = 16; off; off >>= 1) p += __shfl_xor_sync(0xffffffffu, p, off);
        if (lane == 0) sh_sd[n * 2 + isd] = p;
    }
    __syncthreads();

    if (tid == 0) {
        const float s0 = sh_sd[0], d0 = sh_sd[1], s1 = sh_sd[2], d1 = sh_sd[3];
        const float e00 = lrelu(s0 + d0), e10 = lrelu(s1 + d0);
        const float e11 = lrelu(s1 + d1), e01 = lrelu(s0 + d1);
        const float m0 = fmaxf(e00, e10);
        const float w00 = expf(e00 - m0), w10 = expf(e10 - m0);
        const float inv0 = 1.f / (w00 + w10);
        const float m1 = fmaxf(e11, e01);
        const float w11 = expf(e11 - m1), w01 = expf(e01 - m1);
        const float inv1 = 1.f / (w11 + w01);
        sh_w[0] = w00 * inv0; sh_w[1] = w10 * inv0;
        sh_w[2] = w11 * inv1; sh_w[3] = w01 * inv1;
    }
    __syncthreads();

    for (int idx = tid; idx < DIM; idx += 256) {
        const float o0 = sh_w[0] * sh_xp[0][idx] + sh_w[1] * sh_xp[1][idx] + b2[idx];
        const float o1 = sh_w[2] * sh_xp[1][idx] + sh_w[3] * sh_xp[0][idx] + b2[idx];
        xm_h[idx] = __float2half_rn(0.5f * (o0 + o1));
    }
}

// ---------------- launch ----------------
extern "C" void kernel_launch(void* const* d_in, const int* in_sizes, int n_in,
                              void* d_out, int out_size)
{
    const float* audio = (const float*)d_in[0];
    const float* text  = (const float*)d_in[1];
    const float* Wa    = (const float*)d_in[2];
    const float* ba    = (const float*)d_in[3];
    const float* lna_g = (const float*)d_in[4];
    const float* lna_b = (const float*)d_in[5];
    const float* Wt    = (const float*)d_in[6];
    const float* bt    = (const float*)d_in[7];
    const float* lnt_g = (const float*)d_in[8];
    const float* lnt_b = (const float*)d_in[9];
    const float* W1    = (const float*)d_in[10];
    const float* as1   = (const float*)d_in[11];
    const float* ad1   = (const float*)d_in[12];
    const float* b1    = (const float*)d_in[13];
    const float* W2    = (const float*)d_in[14];
    const float* as2   = (const float*)d_in[15];
    const float* ad2   = (const float*)d_in[16];
    const float* b2    = (const float*)d_in[17];
    const float* Wf    = (const float*)d_in[18];
    const float* bf    = (const float*)d_in[19];
    const float* lnf_g = (const float*)d_in[20];
    const float* lnf_b = (const float*)d_in[21];

    __half *Wa_h, *Wt_h, *W1_h, *W2_h, *Wf_h, *nodes_h, *xmean1h, *xm_h;
    float *pre, *x1row01, *xp1, *xp2, *fcb;
    cudaGetSymbolAddress((void**)&Wa_h,    g_Wa_h);
    cudaGetSymbolAddress((void**)&Wt_h,    g_Wt_h);
    cudaGetSymbolAddress((void**)&W1_h,    g_W1_h);
    cudaGetSymbolAddress((void**)&W2_h,    g_W2_h);
    cudaGetSymbolAddress((void**)&Wf_h,    g_Wf_h);
    cudaGetSymbolAddress((void**)&pre,     g_pre);
    cudaGetSymbolAddress((void**)&nodes_h, g_nodes_h);
    cudaGetSymbolAddress((void**)&xmean1h, g_xmean1h);
    cudaGetSymbolAddress((void**)&x1row01, g_x1row01);
    cudaGetSymbolAddress((void**)&xp1,     g_xp1);
    cudaGetSymbolAddress((void**)&xp2,     g_xp2);
    cudaGetSymbolAddress((void**)&xm_h,    g_xm_h);
    cudaGetSymbolAddress((void**)&fcb,     g_fcb);

    cudaFuncSetAttribute(gemm_h<0,0,0>, cudaFuncAttributeMaxDynamicSharedMemorySize, SMEM_BYTES);
    cudaFuncSetAttribute(gemm_h<1,1,1>, cudaFuncAttributeMaxDynamicSharedMemorySize, SMEM_BYTES);
    cudaFuncSetAttribute(gemm_h<0,0,1>, cudaFuncAttributeMaxDynamicSharedMemorySize, SMEM_BYTES);
    cudaFuncSetAttribute(gemm_ha, cudaFuncAttributeMaxDynamicSharedMemorySize, SMEM_BYTES_A);

    const size_t nDD4 = (size_t)DIM * DIM / 4;

    // weight conversions only (inputs stay fp32, converted in-GEMM)
    cvt_kernel<<<2048, 256>>>(Wa, Wa_h, nDD4);
    cvt_kernel<<<2048, 256>>>(Wt, Wt_h, nDD4);
    cvt_kernel<<<4096, 256>>>(W1, W1_h, 2 * nDD4);
    cvt_kernel<<<4096, 256>>>(W2, W2_h, 2 * nDD4);
    cvt_kernel<<<2048, 256>>>(Wf, Wf_h, nDD4);

    dim3 blk(NTHR);

    // proj_audio / proj_text: fp32 A converted in-loop -> interleaved pre-LN rows
    gemm_ha<<<dim3(8, 128), blk, SMEM_BYTES_A>>>(audio, Wa_h, ba, pre, 1024, 1024, 2, 0);
    gemm_ha<<<dim3(8, 128), blk, SMEM_BYTES_A>>>(text,  Wt_h, bt, pre, 1024, 1024, 2, 1);
    // LN + relu -> fp16 nodes
    ln_kernel<<<NNODES / 8, 256>>>(pre, nodes_h, lna_g, lna_b, lnt_g, lnt_b, 1, 1);
    // gat1 + relu + fused pair-mean -> fp16 xmean1 [BATCH, 2*DIM]
    gemm_h<1,1,1><<<dim3(16, 256), blk, SMEM_BYTES>>>(nodes_h, W1_h, b1, xmean1h, 1024, 2048, 1, 0);
    // parallel attention fixup rows 0,1 (patches xmean1 row 0 before gat2)
    fixup1_xp<<<256, 256>>>(nodes_h, W1, xp1);
    fixup1_fin<<<1, 256>>>(xp1, as1, ad1, b1, x1row01, xmean1h);
    // gat2 on pre-meaned input (affine => mean commutes) -> fp16 xm
    gemm_h<0,0,1><<<dim3(8, 128), blk, SMEM_BYTES>>>(xmean1h, W2_h, b2, xm_h, 2048, 1024, 1, 0);
    // parallel exact xm row 0
    fixup2_xp<<<256, 256>>>(x1row01, W2, xp2);
    fixup2_fin<<<1, 256>>>(xp2, as2, ad2, b2, xm_h);
    // fc -> fp32 fcb
    gemm_h<0,0,0><<<dim3(8, 128), blk, SMEM_BYTES>>>(xm_h, Wf_h, bf, fcb, 1024, 1024, 1, 0);
    // final LN -> fp32 out
    ln_kernel<<<BATCH / 8, 256>>>(fcb, (float*)d_out, lnf_g, lnf_b, lnf_g, lnf_b, 0, 0);
}

// round 17
// speedup vs baseline: 2.9392x; 1.0258x over previous
#include <cuda_runtime.h>
#include <cuda_fp16.h>
#include <cstdint>
#include <cstddef>
#include <math.h>

#define BATCH 16384
#define DIM   1024
#define NNODES (2*BATCH)

// ---------------- scratch (static device memory: allowed) ----------------
__device__ __half g_Wa_h   [(size_t)DIM * DIM];
__device__ __half g_Wt_h   [(size_t)DIM * DIM];
__device__ __half g_W1_h   [(size_t)2 * DIM * DIM];
__device__ __half g_W2_h   [(size_t)DIM * 2 * DIM];
__device__ __half g_Wf_h   [(size_t)DIM * DIM];
__device__ __half g_pre_h  [(size_t)NNODES * DIM];     // proj out pre-LN (fp16, interleaved)
__device__ __half g_nodes_h[(size_t)NNODES * DIM];     // post LN+relu (fp16)
__device__ __half g_xmean1h[(size_t)BATCH * 2 * DIM];  // pair-mean of gat1 out (fp16)
__device__ float  g_x1row01[2 * 2 * DIM];              // exact x1 rows 0,1 (fp32)
__device__ float  g_xp1    [2 * 2 * DIM];              // gat1 xp for rows 0,1
__device__ float  g_xp2    [2 * DIM];                  // gat2 xp for rows 0,1
__device__ __half g_xm_h   [(size_t)BATCH * DIM];      // gat2 out (fp16)
__device__ float  g_fcb    [(size_t)BATCH * DIM];      // fc out pre-LN (fp32)

__device__ __forceinline__ void cp_async16(uint32_t smem_dst, const void* gsrc) {
    asm volatile("cp.async.cg.shared.global [%0], [%1], 16;\n"
                 :: "r"(smem_dst), "l"(gsrc));
}

// =====================================================================
// fp16 GEMM (A fp16): C = A @ W^T (+bias, opt relu, opt pair-mean)
// Block 128x128xK32(halves); 8 warps of 32x64; m16n8k16 f16 MMA, fp32 acc;
// 5-stage cp.async ring; 2 CTAs/SM. OUTH: C fp16 else fp32.
// =====================================================================
#define BM2 128
#define BN2 128
#define BK2 32
#define NTHR 256
#define SR 40                              // halves per smem row (80B)
#define A_STG (BM2 * SR)                   // 5120 halves
#define STG_HALFS (2 * A_STG)              // 20480 B
#define NSTAGE 5
#define SMEM_BYTES (NSTAGE * STG_HALFS * 2)    // 102400 B

template<int RELU, int MEAN, int OUTH>
__launch_bounds__(NTHR, 2)
__global__ void gemm_h(const __half* __restrict__ A, const __half* __restrict__ W,
                       const float* __restrict__ bias, void* __restrict__ Cv,
                       int K, int ldc, int rowmul, int rowadd)
{
    extern __shared__ __half smh[];

    const int tid  = threadIdx.x;
    const int warp = tid >> 5;
    const int lane = tid & 31;
    const int g    = lane >> 2;
    const int tg   = lane & 3;
    const int wm   = (warp & 3) * 32;
    const int wn   = (warp >> 2) * 64;
    const int mblk = blockIdx.y * BM2;
    const int nblk = blockIdx.x * BN2;

    uint32_t smem_base;
    {
        void* p = smh;
        smem_base = (uint32_t)__cvta_generic_to_shared(p);
    }

    float acc[2][8][4];
#pragma unroll
    for (int i = 0; i < 2; i++)
#pragma unroll
        for (int j = 0; j < 8; j++)
#pragma unroll
            for (int q = 0; q < 4; q++) acc[i][j][q] = 0.f;

    auto issue = [&](int st, int kb) {
        const int k0 = kb * BK2;
        const uint32_t stg = smem_base + (uint32_t)(st * STG_HALFS) * 2u;
#pragma unroll
        for (int i = 0; i < 2; i++) {
            const int c  = tid + i * NTHR;
            const int m  = c >> 2;
            const int kc = (c & 3) * 8;
            cp_async16(stg + (uint32_t)(m * SR + kc) * 2u,
                       A + (size_t)(mblk + m) * K + k0 + kc);
            cp_async16(stg + (uint32_t)(A_STG + m * SR + kc) * 2u,
                       W + (size_t)(nblk + m) * K + k0 + kc);
        }
    };

    auto compute = [&](int st) {
        const __half* Ast = smh + st * STG_HALFS;
        const __half* Bst = Ast + A_STG;
#pragma unroll
        for (int ks = 0; ks < 2; ks++) {
            const int kb = ks * 16;
            uint32_t a[2][4];
#pragma unroll
            for (int i = 0; i < 2; i++) {
                const int m0 = wm + i * 16;
                a[i][0] = *(const uint32_t*)(Ast + (m0 + g    ) * SR + kb + 2 * tg);
                a[i][1] = *(const uint32_t*)(Ast + (m0 + g + 8) * SR + kb + 2 * tg);
                a[i][2] = *(const uint32_t*)(Ast + (m0 + g    ) * SR + kb + 2 * tg + 8);
                a[i][3] = *(const uint32_t*)(Ast + (m0 + g + 8) * SR + kb + 2 * tg + 8);
            }
            uint32_t b[8][2];
#pragma unroll
            for (int j = 0; j < 8; j++) {
                const int n0 = wn + j * 8;
                b[j][0] = *(const uint32_t*)(Bst + (n0 + g) * SR + kb + 2 * tg);
                b[j][1] = *(const uint32_t*)(Bst + (n0 + g) * SR + kb + 2 * tg + 8);
            }
#pragma unroll
            for (int i = 0; i < 2; i++)
#pragma unroll
                for (int j = 0; j < 8; j++)
                    asm volatile(
                        "mma.sync.aligned.m16n8k16.row.col.f32.f16.f16.f32 "
                        "{%0,%1,%2,%3}, {%4,%5,%6,%7}, {%8,%9}, {%0,%1,%2,%3};\n"
                        : "+f"(acc[i][j][0]), "+f"(acc[i][j][1]),
                          "+f"(acc[i][j][2]), "+f"(acc[i][j][3])
                        : "r"(a[i][0]), "r"(a[i][1]), "r"(a[i][2]), "r"(a[i][3]),
                          "r"(b[j][0]), "r"(b[j][1]));
        }
    };

    const int KT = K / BK2;

#pragma unroll
    for (int p = 0; p < NSTAGE - 1; p++) {
        if (p < KT) issue(p, p);
        asm volatile("cp.async.commit_group;\n" ::);
    }

    for (int kb = 0; kb < KT; kb++) {
        asm volatile("cp.async.wait_group %0;\n" :: "n"(NSTAGE - 2));
        __syncthreads();
        if (kb + NSTAGE - 1 < KT) issue((kb + NSTAGE - 1) % NSTAGE, kb + NSTAGE - 1);
        asm volatile("cp.async.commit_group;\n" ::);
        compute(kb % NSTAGE);
        __syncthreads();
    }

    float* Cf = (float*)Cv;
    __half* Ch = (__half*)Cv;

#pragma unroll
    for (int i = 0; i < 2; i++) {
        const int row_a = mblk + wm + i * 16 + g;
        const int row_b = row_a + 8;
#pragma unroll
        for (int j = 0; j < 8; j++) {
            const int col = nblk + wn + j * 8 + 2 * tg;
            const float2 bv = *(const float2*)(bias + col);
            float o0 = acc[i][j][0] + bv.x;
            float o1 = acc[i][j][1] + bv.y;
            float o2 = acc[i][j][2] + bv.x;
            float o3 = acc[i][j][3] + bv.y;
            if (RELU) {
                o0 = fmaxf(o0, 0.f); o1 = fmaxf(o1, 0.f);
                o2 = fmaxf(o2, 0.f); o3 = fmaxf(o3, 0.f);
            }
            if (MEAN) {
                const float m0 = 0.5f * (o0 + __shfl_xor_sync(0xffffffffu, o0, 4));
                const float m1 = 0.5f * (o1 + __shfl_xor_sync(0xffffffffu, o1, 4));
                const float m2 = 0.5f * (o2 + __shfl_xor_sync(0xffffffffu, o2, 4));
                const float m3 = 0.5f * (o3 + __shfl_xor_sync(0xffffffffu, o3, 4));
                if ((g & 1) == 0) {
                    const size_t ra = (size_t)(row_a >> 1) * ldc + col;
                    const size_t rb = (size_t)(row_b >> 1) * ldc + col;
                    if (OUTH) {
                        *(__half2*)(Ch + ra) = __floats2half2_rn(m0, m1);
                        *(__half2*)(Ch + rb) = __floats2half2_rn(m2, m3);
                    } else {
                        *(float2*)(Cf + ra) = make_float2(m0, m1);
                        *(float2*)(Cf + rb) = make_float2(m2, m3);
                    }
                }
            } else {
                const size_t ca = (size_t)(rowmul * row_a + rowadd) * ldc + col;
                const size_t cb = (size_t)(rowmul * row_b + rowadd) * ldc + col;
                if (OUTH) {
                    *(__half2*)(Ch + ca) = __floats2half2_rn(o0, o1);
                    *(__half2*)(Ch + cb) = __floats2half2_rn(o2, o3);
                } else {
                    *(float2*)(Cf + ca) = make_float2(o0, o1);
                    *(float2*)(Cf + cb) = make_float2(o2, o3);
                }
            }
        }
    }
}

// =====================================================================
// fp32-A proj GEMM: A fp32 (converted post-LDS), W fp16, OUTPUT fp16.
// blockIdx.z selects (A0,W0,bias0,rowadd=0) or (A1,W1,bias1,rowadd=1).
// 3-stage ring; 2 CTAs/SM. Writes interleaved rows (rowmul=2 implied).
// =====================================================================
#define ASRF 40                                // floats per A smem row (160B)
#define A_STGF_BYTES (BM2 * ASRF * 4)          // 20480 B
#define B_STGH_BYTES (BM2 * SR * 2)            // 10240 B
#define STGA_BYTES (A_STGF_BYTES + B_STGH_BYTES)   // 30720 B
#define NSTAGEA 3
#define SMEM_BYTES_A (NSTAGEA * STGA_BYTES)    // 92160 B

__launch_bounds__(NTHR, 2)
__global__ void gemm_proj(const float* __restrict__ A0, const float* __restrict__ A1,
                          const __half* __restrict__ W0, const __half* __restrict__ W1,
                          const float* __restrict__ b0, const float* __restrict__ b1,
                          __half* __restrict__ C, int K, int ldc)
{
    extern __shared__ char smc[];

    const int z = blockIdx.z;
    const float*  A    = z ? A1 : A0;
    const __half* W    = z ? W1 : W0;
    const float*  bias = z ? b1 : b0;

    const int tid  = threadIdx.x;
    const int warp = tid >> 5;
    const int lane = tid & 31;
    const int g    = lane >> 2;
    const int tg   = lane & 3;
    const int wm   = (warp & 3) * 32;
    const int wn   = (warp >> 2) * 64;
    const int mblk = blockIdx.y * BM2;
    const int nblk = blockIdx.x * BN2;

    uint32_t smem_base;
    {
        void* p = smc;
        smem_base = (uint32_t)__cvta_generic_to_shared(p);
    }

    float acc[2][8][4];
#pragma unroll
    for (int i = 0; i < 2; i++)
#pragma unroll
        for (int j = 0; j < 8; j++)
#pragma unroll
            for (int q = 0; q < 4; q++) acc[i][j][q] = 0.f;

    auto issue = [&](int st, int kb) {
        const int k0 = kb * BK2;
        const uint32_t stg = smem_base + (uint32_t)(st * STGA_BYTES);
#pragma unroll
        for (int i = 0; i < 4; i++) {
            const int c  = tid + i * NTHR;
            const int m  = c >> 3;
            const int kc = (c & 7) * 4;
            cp_async16(stg + (uint32_t)(m * ASRF + kc) * 4u,
                       A + (size_t)(mblk + m) * K + k0 + kc);
        }
#pragma unroll
        for (int i = 0; i < 2; i++) {
            const int c  = tid + i * NTHR;
            const int m  = c >> 2;
            const int kc = (c & 3) * 8;
            cp_async16(stg + A_STGF_BYTES + (uint32_t)(m * SR + kc) * 2u,
                       W + (size_t)(nblk + m) * K + k0 + kc);
        }
    };

    auto compute = [&](int st) {
        const float*  Ast = (const float*)(smc + st * STGA_BYTES);
        const __half* Bst = (const __half*)(smc + st * STGA_BYTES + A_STGF_BYTES);
#pragma unroll
        for (int ks = 0; ks < 2; ks++) {
            const int kb = ks * 16;
            uint32_t a[2][4];
#pragma unroll
            for (int i = 0; i < 2; i++) {
                const int m0 = wm + i * 16;
                const float2 p00 = *(const float2*)(Ast + (m0 + g    ) * ASRF + kb + 2 * tg);
                const float2 p10 = *(const float2*)(Ast + (m0 + g + 8) * ASRF + kb + 2 * tg);
                const float2 p01 = *(const float2*)(Ast + (m0 + g    ) * ASRF + kb + 2 * tg + 8);
                const float2 p11 = *(const float2*)(Ast + (m0 + g + 8) * ASRF + kb + 2 * tg + 8);
                const __half2 h00 = __floats2half2_rn(p00.x, p00.y);
                const __half2 h10 = __floats2half2_rn(p10.x, p10.y);
                const __half2 h01 = __floats2half2_rn(p01.x, p01.y);
                const __half2 h11 = __floats2half2_rn(p11.x, p11.y);
                a[i][0] = *(const uint32_t*)&h00;
                a[i][1] = *(const uint32_t*)&h10;
                a[i][2] = *(const uint32_t*)&h01;
                a[i][3] = *(const uint32_t*)&h11;
            }
            uint32_t b[8][2];
#pragma unroll
            for (int j = 0; j < 8; j++) {
                const int n0 = wn + j * 8;
                b[j][0] = *(const uint32_t*)(Bst + (n0 + g) * SR + kb + 2 * tg);
                b[j][1] = *(const uint32_t*)(Bst + (n0 + g) * SR + kb + 2 * tg + 8);
            }
#pragma unroll
            for (int i = 0; i < 2; i++)
#pragma unroll
                for (int j = 0; j < 8; j++)
                    asm volatile(
                        "mma.sync.aligned.m16n8k16.row.col.f32.f16.f16.f32 "
                        "{%0,%1,%2,%3}, {%4,%5,%6,%7}, {%8,%9}, {%0,%1,%2,%3};\n"
                        : "+f"(acc[i][j][0]), "+f"(acc[i][j][1]),
                          "+f"(acc[i][j][2]), "+f"(acc[i][j][3])
                        : "r"(a[i][0]), "r"(a[i][1]), "r"(a[i][2]), "r"(a[i][3]),
                          "r"(b[j][0]), "r"(b[j][1]));
        }
    };

    const int KT = K / BK2;

#pragma unroll
    for (int p = 0; p < NSTAGEA - 1; p++) {
        if (p < KT) issue(p, p);
        asm volatile("cp.async.commit_group;\n" ::);
    }

    for (int kb = 0; kb < KT; kb++) {
        asm volatile("cp.async.wait_group %0;\n" :: "n"(NSTAGEA - 2));
        __syncthreads();
        if (kb + NSTAGEA - 1 < KT) issue((kb + NSTAGEA - 1) % NSTAGEA, kb + NSTAGEA - 1);
        asm volatile("cp.async.commit_group;\n" ::);
        compute(kb % NSTAGEA);
        __syncthreads();
    }

#pragma unroll
    for (int i = 0; i < 2; i++) {
        const int row_a = mblk + wm + i * 16 + g;
        const int row_b = row_a + 8;
#pragma unroll
        for (int j = 0; j < 8; j++) {
            const int col = nblk + wn + j * 8 + 2 * tg;
            const float2 bv = *(const float2*)(bias + col);
            const float o0 = acc[i][j][0] + bv.x;
            const float o1 = acc[i][j][1] + bv.y;
            const float o2 = acc[i][j][2] + bv.x;
            const float o3 = acc[i][j][3] + bv.y;
            const size_t ca = (size_t)(2 * row_a + z) * ldc + col;
            const size_t cb = (size_t)(2 * row_b + z) * ldc + col;
            *(__half2*)(C + ca) = __floats2half2_rn(o0, o1);
            *(__half2*)(C + cb) = __floats2half2_rn(o2, o3);
        }
    }
}

// ---------------- fp32 -> fp16 conversion (weights) ----------------
__global__ void cvt_kernel(const float* __restrict__ in, __half* __restrict__ out,
                           size_t n4)
{
    const size_t stride = (size_t)gridDim.x * blockDim.x;
    for (size_t i = (size_t)blockIdx.x * blockDim.x + threadIdx.x; i < n4; i += stride) {
        const float4 v = ((const float4*)in)[i];
        const __half2 h0 = __floats2half2_rn(v.x, v.y);
        const __half2 h1 = __floats2half2_rn(v.z, v.w);
        uint2 u;
        u.x = *(const uint32_t*)&h0;
        u.y = *(const uint32_t*)&h1;
        ((uint2*)out)[i] = u;
    }
}

// ---------------- LayerNorm, warp-per-row; fp16 or fp32 in, fp16 or fp32 out ------
__global__ void ln_kernel(const void* __restrict__ inv, void* __restrict__ outv,
                          const float* __restrict__ g_e, const float* __restrict__ b_e,
                          const float* __restrict__ g_o, const float* __restrict__ b_o,
                          int relu, int inh, int outh)
{
    const int warp = threadIdx.x >> 5;
    const int lane = threadIdx.x & 31;
    const int row  = blockIdx.x * 8 + warp;
    const float* gg = (row & 1) ? g_o : g_e;
    const float* bb = (row & 1) ? b_o : b_e;

    float4 v[8];
    float s = 0.f, q = 0.f;
    if (inh) {
        const uint2* rin = (const uint2*)((const __half*)inv + (size_t)row * DIM);
#pragma unroll
        for (int i = 0; i < 8; i++) {
            const uint2 u = rin[lane + 32 * i];
            const __half2 h0 = *(const __half2*)&u.x;
            const __half2 h1 = *(const __half2*)&u.y;
            const float2 f0 = __half22float2(h0);
            const float2 f1 = __half22float2(h1);
            v[i] = make_float4(f0.x, f0.y, f1.x, f1.y);
            s += v[i].x + v[i].y + v[i].z + v[i].w;
            q += v[i].x*v[i].x + v[i].y*v[i].y + v[i].z*v[i].z + v[i].w*v[i].w;
        }
    } else {
        const float4* rin = (const float4*)((const float*)inv + (size_t)row * DIM);
#pragma unroll
        for (int i = 0; i < 8; i++) {
            v[i] = rin[lane + 32 * i];
            s += v[i].x + v[i].y + v[i].z + v[i].w;
            q += v[i].x*v[i].x + v[i].y*v[i].y + v[i].z*v[i].z + v[i].w*v[i].w;
        }
    }
#pragma unroll
    for (int off = 16; off; off >>= 1) {
        s += __shfl_xor_sync(0xffffffffu, s, off);
        q += __shfl_xor_sync(0xffffffffu, q, off);
    }
    const float mu = s * (1.0f / DIM);
    const float var = q * (1.0f / DIM) - mu * mu;
    const float rs = rsqrtf(var + 1e-5f);

#pragma unroll
    for (int i = 0; i < 8; i++) {
        const int c4 = lane + 32 * i;
        const float4 gv = ((const float4*)gg)[c4];
        const float4 bv = ((const float4*)bb)[c4];
        float4 o;
        o.x = (v[i].x - mu) * rs * gv.x + bv.x;
        o.y = (v[i].y - mu) * rs * gv.y + bv.y;
        o.z = (v[i].z - mu) * rs * gv.z + bv.z;
        o.w = (v[i].w - mu) * rs * gv.w + bv.w;
        if (relu) {
            o.x = fmaxf(o.x, 0.f); o.y = fmaxf(o.y, 0.f);
            o.z = fmaxf(o.z, 0.f); o.w = fmaxf(o.w, 0.f);
        }
        if (outh) {
            const __half2 h0 = __floats2half2_rn(o.x, o.y);
            const __half2 h1 = __floats2half2_rn(o.z, o.w);
            uint2 u;
            u.x = *(const uint32_t*)&h0;
            u.y = *(const uint32_t*)&h1;
            ((uint2*)((__half*)outv + (size_t)row * DIM))[c4] = u;
        } else {
            ((float4*)((float*)outv + (size_t)row * DIM))[c4] = o;
        }
    }
}

__device__ __forceinline__ float lrelu(float v) { return v > 0.f ? v : 0.2f * v; }

// ---------------- gat1 fixup phase A ----------------
__global__ void fixup1_xp(const __half* __restrict__ nodes_h, const float* __restrict__ W1,
                          float* __restrict__ xp1)
{
    const int w = blockIdx.x * 8 + (threadIdx.x >> 5);
    const int lane = threadIdx.x & 31;
#pragma unroll
    for (int rep = 0; rep < 2; rep++) {
        const int o = w + rep * 2048;
        const int n = o >> 11, oc = o & 2047;
        const float* wr = W1 + (size_t)oc * DIM;
        const __half* nr = nodes_h + (size_t)n * DIM;
        float p = 0.f;
        for (int k = lane; k < DIM; k += 32) p += __half2float(nr[k]) * wr[k];
#pragma unroll
        for (int off = 16; off; off >>= 1) p += __shfl_xor_sync(0xffffffffu, p, off);
        if (lane == 0) xp1[o] = p;
    }
}

// ---------------- gat1 fixup phase B ----------------
__global__ void fixup1_fin(const float* __restrict__ xp1,
                           const float* __restrict__ as1, const float* __restrict__ ad1,
                           const float* __restrict__ b1, float* __restrict__ x1row01,
                           __half* __restrict__ xmean1h)
{
    __shared__ float sh_xp[2][2 * DIM];
    __shared__ float sh_sd[8];
    __shared__ float sh_w[8];
    const int tid = threadIdx.x, warp = tid >> 5, lane = tid & 31;

    for (int i = tid; i < 4096; i += 256) sh_xp[i >> 11][i & 2047] = xp1[i];
    __syncthreads();

    if (warp < 8) {
        const int n = warp >> 2, h = (warp >> 1) & 1, isd = warp & 1;
        const float* av = (isd ? ad1 : as1) + h * DIM;
        float p = 0.f;
        for (int k = lane; k < DIM; k += 32) p += sh_xp[n][h * DIM + k] * av[k];
#pragma unroll
        for (int off = 16; off; off >>= 1) p += __shfl_xor_sync(0xffffffffu, p, off);
        if (lane == 0) sh_sd[n * 4 + h * 2 + isd] = p;
    }
    __syncthreads();

    if (tid == 0) {
#pragma unroll
        for (int h = 0; h < 2; h++) {
            const float s0 = sh_sd[0*4 + h*2 + 0], d0 = sh_sd[0*4 + h*2 + 1];
            const float s1 = sh_sd[1*4 + h*2 + 0], d1 = sh_sd[1*4 + h*2 + 1];
            const float e00 = lrelu(s0 + d0), e10 = lrelu(s1 + d0);
            const float e11 = lrelu(s1 + d1), e01 = lrelu(s0 + d1);
            const float m0 = fmaxf(e00, e10);
            const float w00 = expf(e00 - m0), w10 = expf(e10 - m0);
            const float inv0 = 1.f / (w00 + w10);
            const float m1 = fmaxf(e11, e01);
            const float w11 = expf(e11 - m1), w01 = expf(e01 - m1);
            const float inv1 = 1.f / (w11 + w01);
            sh_w[h*4+0] = w00 * inv0;
            sh_w[h*4+1] = w10 * inv0;
            sh_w[h*4+2] = w11 * inv1;
            sh_w[h*4+3] = w01 * inv1;
        }
    }
    __syncthreads();

    for (int idx = tid; idx < 2 * DIM; idx += 256) {
        const int h = idx >> 10;
        const float o0 = sh_w[h*4+0] * sh_xp[0][idx] + sh_w[h*4+1] * sh_xp[1][idx];
        const float o1 = sh_w[h*4+2] * sh_xp[1][idx] + sh_w[h*4+3] * sh_xp[0][idx];
        const float r0 = fmaxf(o0 + b1[idx], 0.f);
        const float r1 = fmaxf(o1 + b1[idx], 0.f);
        x1row01[idx]           = r0;
        x1row01[2 * DIM + idx] = r1;
        xmean1h[idx] = __float2half_rn(0.5f * (r0 + r1));
    }
}

// ---------------- gat2 fixup phase A ----------------
__global__ void fixup2_xp(const float* __restrict__ x1row01, const float* __restrict__ W2,
                          float* __restrict__ xp2)
{
    const int o = blockIdx.x * 8 + (threadIdx.x >> 5);
    const int lane = threadIdx.x & 31;
    const int n = o >> 10, oc = o & 1023;
    const float* wr = W2 + (size_t)oc * (2 * DIM);
    const float* xr = x1row01 + (size_t)n * (2 * DIM);
    float p = 0.f;
    for (int k = lane; k < 2 * DIM; k += 32) p += xr[k] * wr[k];
#pragma unroll
    for (int off = 16; off; off >>= 1) p += __shfl_xor_sync(0xffffffffu, p, off);
    if (lane == 0) xp2[o] = p;
}

// ---------------- gat2 fixup phase B ----------------
__global__ void fixup2_fin(const float* __restrict__ xp2,
                           const float* __restrict__ as2, const float* __restrict__ ad2,
                           const float* __restrict__ b2, __half* __restrict__ xm_h)
{
    __shared__ float sh_xp[2][DIM];
    __shared__ float sh_sd[4];
    __shared__ float sh_w[4];
    const int tid = threadIdx.x, warp = tid >> 5, lane = tid & 31;

    for (int i = tid; i < 2 * DIM; i += 256) sh_xp[i >> 10][i & 1023] = xp2[i];
    __syncthreads();

    if (warp < 4) {
        const int n = warp >> 1, isd = warp & 1;
        const float* av = isd ? ad2 : as2;
        float p = 0.f;
        for (int k = lane; k < DIM; k += 32) p += sh_xp[n][k] * av[k];
#pragma unroll
        for (int off = 16; off; off >>= 1) p += __shfl_xor_sync(0xffffffffu, p, off);
        if (lane == 0) sh_sd[n * 2 + isd] = p;
    }
    __syncthreads();

    if (tid == 0) {
        const float s0 = sh_sd[0], d0 = sh_sd[1], s1 = sh_sd[2], d1 = sh_sd[3];
        const float e00 = lrelu(s0 + d0), e10 = lrelu(s1 + d0);
        const float e11 = lrelu(s1 + d1), e01 = lrelu(s0 + d1);
        const float m0 = fmaxf(e00, e10);
        const float w00 = expf(e00 - m0), w10 = expf(e10 - m0);
        const float inv0 = 1.f / (w00 + w10);
        const float m1 = fmaxf(e11, e01);
        const float w11 = expf(e11 - m1), w01 = expf(e01 - m1);
        const float inv1 = 1.f / (w11 + w01);
        sh_w[0] = w00 * inv0; sh_w[1] = w10 * inv0;
        sh_w[2] = w11 * inv1; sh_w[3] = w01 * inv1;
    }
    __syncthreads();

    for (int idx = tid; idx < DIM; idx += 256) {
        const float o0 = sh_w[0] * sh_xp[0][idx] + sh_w[1] * sh_xp[1][idx] + b2[idx];
        const float o1 = sh_w[2] * sh_xp[1][idx] + sh_w[3] * sh_xp[0][idx] + b2[idx];
        xm_h[idx] = __float2half_rn(0.5f * (o0 + o1));
    }
}

// ---------------- launch ----------------
extern "C" void kernel_launch(void* const* d_in, const int* in_sizes, int n_in,
                              void* d_out, int out_size)
{
    const float* audio = (const float*)d_in[0];
    const float* text  = (const float*)d_in[1];
    const float* Wa    = (const float*)d_in[2];
    const float* ba    = (const float*)d_in[3];
    const float* lna_g = (const float*)d_in[4];
    const float* lna_b = (const float*)d_in[5];
    const float* Wt    = (const float*)d_in[6];
    const float* bt    = (const float*)d_in[7];
    const float* lnt_g = (const float*)d_in[8];
    const float* lnt_b = (const float*)d_in[9];
    const float* W1    = (const float*)d_in[10];
    const float* as1   = (const float*)d_in[11];
    const float* ad1   = (const float*)d_in[12];
    const float* b1    = (const float*)d_in[13];
    const float* W2    = (const float*)d_in[14];
    const float* as2   = (const float*)d_in[15];
    const float* ad2   = (const float*)d_in[16];
    const float* b2    = (const float*)d_in[17];
    const float* Wf    = (const float*)d_in[18];
    const float* bf    = (const float*)d_in[19];
    const float* lnf_g = (const float*)d_in[20];
    const float* lnf_b = (const float*)d_in[21];

    __half *Wa_h, *Wt_h, *W1_h, *W2_h, *Wf_h, *pre_h, *nodes_h, *xmean1h, *xm_h;
    float *x1row01, *xp1, *xp2, *fcb;
    cudaGetSymbolAddress((void**)&Wa_h,    g_Wa_h);
    cudaGetSymbolAddress((void**)&Wt_h,    g_Wt_h);
    cudaGetSymbolAddress((void**)&W1_h,    g_W1_h);
    cudaGetSymbolAddress((void**)&W2_h,    g_W2_h);
    cudaGetSymbolAddress((void**)&Wf_h,    g_Wf_h);
    cudaGetSymbolAddress((void**)&pre_h,   g_pre_h);
    cudaGetSymbolAddress((void**)&nodes_h, g_nodes_h);
    cudaGetSymbolAddress((void**)&xmean1h, g_xmean1h);
    cudaGetSymbolAddress((void**)&x1row01, g_x1row01);
    cudaGetSymbolAddress((void**)&xp1,     g_xp1);
    cudaGetSymbolAddress((void**)&xp2,     g_xp2);
    cudaGetSymbolAddress((void**)&xm_h,    g_xm_h);
    cudaGetSymbolAddress((void**)&fcb,     g_fcb);

    cudaFuncSetAttribute(gemm_h<0,0,0>, cudaFuncAttributeMaxDynamicSharedMemorySize, SMEM_BYTES);
    cudaFuncSetAttribute(gemm_h<1,1,1>, cudaFuncAttributeMaxDynamicSharedMemorySize, SMEM_BYTES);
    cudaFuncSetAttribute(gemm_h<0,0,1>, cudaFuncAttributeMaxDynamicSharedMemorySize, SMEM_BYTES);
    cudaFuncSetAttribute(gemm_proj, cudaFuncAttributeMaxDynamicSharedMemorySize, SMEM_BYTES_A);

    const size_t nDD4 = (size_t)DIM * DIM / 4;

    // weight conversions (inputs stay fp32, converted in-GEMM)
    cvt_kernel<<<2048, 256>>>(Wa, Wa_h, nDD4);
    cvt_kernel<<<2048, 256>>>(Wt, Wt_h, nDD4);
    cvt_kernel<<<4096, 256>>>(W1, W1_h, 2 * nDD4);
    cvt_kernel<<<4096, 256>>>(W2, W2_h, 2 * nDD4);
    cvt_kernel<<<2048, 256>>>(Wf, Wf_h, nDD4);

    dim3 blk(NTHR);

    // both proj layers in ONE launch (z=0 audio, z=1 text) -> fp16 interleaved pre
    gemm_proj<<<dim3(8, 128, 2), blk, SMEM_BYTES_A>>>(audio, text, Wa_h, Wt_h, ba, bt,
                                                      pre_h, 1024, 1024);
    // LN + relu (fp16 in) -> fp16 nodes
    ln_kernel<<<NNODES / 8, 256>>>(pre_h, nodes_h, lna_g, lna_b, lnt_g, lnt_b, 1, 1, 1);
    // gat1 + relu + fused pair-mean -> fp16 xmean1 [BATCH, 2*DIM]
    gemm_h<1,1,1><<<dim3(16, 256), blk, SMEM_BYTES>>>(nodes_h, W1_h, b1, xmean1h, 1024, 2048, 1, 0);
    // parallel attention fixup rows 0,1 (patches xmean1 row 0 before gat2)
    fixup1_xp<<<256, 256>>>(nodes_h, W1, xp1);
    fixup1_fin<<<1, 256>>>(xp1, as1, ad1, b1, x1row01, xmean1h);
    // gat2 on pre-meaned input (affine => mean commutes) -> fp16 xm
    gemm_h<0,0,1><<<dim3(8, 128), blk, SMEM_BYTES>>>(xmean1h, W2_h, b2, xm_h, 2048, 1024, 1, 0);
    // parallel exact xm row 0
    fixup2_xp<<<256, 256>>>(x1row01, W2, xp2);
    fixup2_fin<<<1, 256>>>(xp2, as2, ad2, b2, xm_h);
    // fc -> fp32 fcb
    gemm_h<0,0,0><<<dim3(8, 128), blk, SMEM_BYTES>>>(xm_h, Wf_h, bf, fcb, 1024, 1024, 1, 0);
    // final LN (fp32 in) -> fp32 out
    ln_kernel<<<BATCH / 8, 256>>>(fcb, (float*)d_out, lnf_g, lnf_b, lnf_g, lnf_b, 0, 0, 0);
}